// round 14
// baseline (speedup 1.0000x reference)
#include <cuda_runtime.h>
#include <cuda_bf16.h>
#include <math.h>
#include <stdint.h>

#define BQ   8192
#define NCTX 4096
#define DDIM 2048
#define MDIM 1024
#define CDIM 64
#define KCLS 100

#define SW(off) ((off) ^ (((off) >> 3) & 0x70))

__device__ __forceinline__ uint32_t smem_u32(const void* p) {
    uint32_t a;
    asm("{ .reg .u64 t; cvta.to.shared.u64 t, %1; cvt.u32.u64 %0, t; }" : "=r"(a) : "l"(p));
    return a;
}
__device__ __forceinline__ void cp_async16(uint32_t saddr, const void* gptr) {
    asm volatile("cp.async.cg.shared.global [%0], [%1], 16;" :: "r"(saddr), "l"(gptr) : "memory");
}
__device__ __forceinline__ void cp_commit() {
    asm volatile("cp.async.commit_group;" ::: "memory");
}
__device__ __forceinline__ void ldmx4(uint32_t* r, uint32_t addr) {
    asm volatile("ldmatrix.sync.aligned.m8n8.x4.shared.b16 {%0,%1,%2,%3}, [%4];"
                 : "=r"(r[0]), "=r"(r[1]), "=r"(r[2]), "=r"(r[3]) : "r"(addr));
}
__device__ __forceinline__ void mma16816(float* c, const uint32_t* a, uint32_t b0, uint32_t b1) {
    asm volatile("mma.sync.aligned.m16n8k16.row.col.f32.bf16.bf16.f32 "
                 "{%0,%1,%2,%3}, {%4,%5,%6,%7}, {%8,%9}, {%0,%1,%2,%3};"
                 : "+f"(c[0]), "+f"(c[1]), "+f"(c[2]), "+f"(c[3])
                 : "r"(a[0]), "r"(a[1]), "r"(a[2]), "r"(a[3]), "r"(b0), "r"(b1));
}
__device__ __forceinline__ void imma16832(int* c, const uint32_t* a, uint32_t b0, uint32_t b1) {
    asm volatile("mma.sync.aligned.m16n8k32.row.col.s32.s8.s8.s32 "
                 "{%0,%1,%2,%3}, {%4,%5,%6,%7}, {%8,%9}, {%0,%1,%2,%3};"
                 : "+r"(c[0]), "+r"(c[1]), "+r"(c[2]), "+r"(c[3])
                 : "r"(a[0]), "r"(a[1]), "r"(a[2]), "r"(a[3]), "r"(b0), "r"(b1));
}
__device__ __forceinline__ uint32_t pack_bf2(__nv_bfloat16 a, __nv_bfloat16 b) {
    __nv_bfloat162 t = __halves2bfloat162(a, b);
    return *reinterpret_cast<uint32_t*>(&t);
}
// 2-term fixed-point int8 split: x = a/16 + b/4064 + t, |t| <= 0.5/4064 = 1.23e-4
// (residual after a-quant is in [-1/32, 1/32]; 4064/32 = 127 exactly -> no overflow)
#define QB_SCALE 4064.0f
__device__ __forceinline__ void quant2(float v, char& a, char& b) {
    float fa = fminf(fmaxf(rintf(v * 16.0f), -127.0f), 127.0f);
    float fb = fminf(fmaxf(rintf((v - fa * 0.0625f) * QB_SCALE), -127.0f), 127.0f);
    a = (char)(int)fa;
    b = (char)(int)fb;
}

// ===========================================================================
// Device scratch
// ===========================================================================
__device__ __align__(256) __nv_bfloat16 g_emb1[(size_t)NCTX * DDIM];
__device__ __align__(256) __nv_bfloat16 g_emb2[(size_t)NCTX * DDIM];
__device__ __align__(256) __nv_bfloat16 g_wk1t[(size_t)MDIM * DDIM];
__device__ __align__(256) __nv_bfloat16 g_wk2t[(size_t)MDIM * DDIM];
__device__ __align__(256) __nv_bfloat16 g_wv1t[(size_t)MDIM * DDIM];
__device__ __align__(256) __nv_bfloat16 g_wv2t[(size_t)MDIM * DDIM];
__device__ __align__(256) __nv_bfloat16 g_f1[(size_t)BQ * DDIM];
__device__ __align__(256) __nv_bfloat16 g_f2[(size_t)BQ * DDIM];
__device__ __align__(256) __nv_bfloat16 g_f3[(size_t)BQ * DDIM];
__device__ __align__(256) __nv_bfloat16 g_wq1t[(size_t)MDIM * DDIM];
__device__ __align__(256) __nv_bfloat16 g_wq2t[(size_t)MDIM * DDIM];
__device__ __align__(256) __nv_bfloat16 g_wq3t[(size_t)MDIM * DDIM];
__device__ __align__(256) float         g_v [(size_t)NCTX * MDIM];
__device__ __align__(256) float         g_q [(size_t)BQ * MDIM];
__device__ __align__(256) char          g_qa[(size_t)BQ * MDIM];
__device__ __align__(256) char          g_qb[(size_t)BQ * MDIM];
__device__ __align__(256) char          g_ka[(size_t)NCTX * MDIM];
__device__ __align__(256) char          g_kb[(size_t)NCTX * MDIM];
__device__ __align__(256) __nv_bfloat16 g_v1t[(size_t)MDIM * NCTX];
__device__ __align__(256) __nv_bfloat16 g_v2t[(size_t)MDIM * NCTX];
__device__ __align__(256) float         g_S [(size_t)BQ * NCTX];
__device__ __align__(256) __nv_bfloat16 g_P1[(size_t)BQ * NCTX];
__device__ __align__(256) __nv_bfloat16 g_P2[(size_t)BQ * NCTX];
__device__ __align__(256) float         g_O [(size_t)BQ * MDIM];

// ===========================================================================
// bf16 HMMA 128x256 mainloop (R8 config: 256 thr, 8 warps 2m x 4n, 64x64)
// smem/stage 48KB: A1@0 A2@8K B1@16K B2@32K. STG=3.
// ===========================================================================
#define STG 3
#define L2_STAGE 49152

struct L2Out {
    float acc[4][8][4];
};

__device__ __forceinline__ void l2_mainloop(
    char* smem, const __nv_bfloat16* A1, const __nv_bfloat16* A2,
    const __nv_bfloat16* B1, const __nv_bfloat16* B2,
    int bx, int by, int Kd, L2Out& o)
{
    const int tid  = threadIdx.x;
    const int lane = tid & 31;
    const int wid  = tid >> 5;
    const int wm   = wid & 1;
    const int wn   = wid >> 1;

    const uint32_t sbase = smem_u32(smem);
    const int nstages = Kd >> 5;

    const int lr = tid >> 2, lc = tid & 3;
    const uint32_t aso0 = SW((uint32_t)(lr * 64 + lc * 16));
    const uint32_t aso1 = SW((uint32_t)((lr + 64) * 64 + lc * 16));
    uint32_t bso[4];
    #pragma unroll
    for (int h = 0; h < 4; h++) bso[h] = SW((uint32_t)((lr + h * 64) * 64 + lc * 16));
    const size_t ag0 = ((size_t)by * 128 + lr) * Kd + lc * 8;
    const size_t bg0 = ((size_t)bx * 256 + lr) * Kd + lc * 8;
    const size_t rstep = (size_t)64 * Kd;

    const int a_r = lane & 15;
    const int a_h = (lane >> 4) * 16;
    const int b_r = (lane & 7) | ((lane >> 1) & 8);
    const int b_h = ((lane >> 3) & 1) * 16;

    #pragma unroll
    for (int i = 0; i < 4; i++)
        #pragma unroll
        for (int j = 0; j < 8; j++)
            #pragma unroll
            for (int q = 0; q < 4; q++) o.acc[i][j][q] = 0.0f;

    auto issue = [&](int s) {
        const uint32_t sb = sbase + (uint32_t)((s % STG) * L2_STAGE);
        const size_t kb = (size_t)s * 32;
        cp_async16(sb + aso0,        A1 + ag0 + kb);
        cp_async16(sb + aso1,        A1 + ag0 + rstep + kb);
        cp_async16(sb + 8192 + aso0, A2 + ag0 + kb);
        cp_async16(sb + 8192 + aso1, A2 + ag0 + rstep + kb);
        #pragma unroll
        for (int h = 0; h < 4; h++) {
            cp_async16(sb + 16384 + bso[h], B1 + bg0 + h * rstep + kb);
            cp_async16(sb + 32768 + bso[h], B2 + bg0 + h * rstep + kb);
        }
        cp_commit();
    };

    issue(0);
    if (nstages > 1) issue(1);

    for (int s = 0; s < nstages; s++) {
        if (s + 2 < nstages) issue(s + 2);
        const int after = nstages - 1 - s;
        if (after >= 2)      asm volatile("cp.async.wait_group 2;" ::: "memory");
        else if (after == 1) asm volatile("cp.async.wait_group 1;" ::: "memory");
        else                 asm volatile("cp.async.wait_group 0;" ::: "memory");
        __syncthreads();

        const uint32_t sb = sbase + (uint32_t)((s % STG) * L2_STAGE);
        #pragma unroll
        for (int kk = 0; kk < 2; kk++) {
            uint32_t a1f[4][4], a2f[4][4], bf[4][4];
            #pragma unroll
            for (int tm = 0; tm < 4; tm++) {
                const uint32_t off = SW((uint32_t)((wm * 64 + tm * 16 + a_r) * 64 + kk * 32 + a_h));
                ldmx4(a1f[tm], sb + off);
                ldmx4(a2f[tm], sb + 8192 + off);
            }
            #pragma unroll
            for (int tn = 0; tn < 4; tn++) {
                const uint32_t off = SW((uint32_t)((wn * 64 + tn * 16 + b_r) * 64 + kk * 32 + b_h));
                ldmx4(bf[tn], sb + 16384 + off);
            }
            #pragma unroll
            for (int tm = 0; tm < 4; tm++)
                #pragma unroll
                for (int n8 = 0; n8 < 8; n8++)
                    mma16816(o.acc[tm][n8], a1f[tm], bf[n8 >> 1][(n8 & 1) * 2], bf[n8 >> 1][(n8 & 1) * 2 + 1]);
            #pragma unroll
            for (int tm = 0; tm < 4; tm++)
                #pragma unroll
                for (int n8 = 0; n8 < 8; n8++)
                    mma16816(o.acc[tm][n8], a2f[tm], bf[n8 >> 1][(n8 & 1) * 2], bf[n8 >> 1][(n8 & 1) * 2 + 1]);
            #pragma unroll
            for (int tn = 0; tn < 4; tn++) {
                const uint32_t off = SW((uint32_t)((wn * 64 + tn * 16 + b_r) * 64 + kk * 32 + b_h));
                ldmx4(bf[tn], sb + 32768 + off);
            }
            #pragma unroll
            for (int tm = 0; tm < 4; tm++)
                #pragma unroll
                for (int n8 = 0; n8 < 8; n8++)
                    mma16816(o.acc[tm][n8], a1f[tm], bf[n8 >> 1][(n8 & 1) * 2], bf[n8 >> 1][(n8 & 1) * 2 + 1]);
        }
        __syncthreads();
    }
}

// fp32-output variant (O GEMM)
__global__ __launch_bounds__(256, 1)
void hmma2_kernel(const __nv_bfloat16* __restrict__ A1, const __nv_bfloat16* __restrict__ A2,
                  const __nv_bfloat16* __restrict__ B1, const __nv_bfloat16* __restrict__ B2,
                  float* __restrict__ C, int N, int Kd, float alpha)
{
    extern __shared__ char smem[];
    const int lane = threadIdx.x & 31;
    const int wid  = threadIdx.x >> 5;
    L2Out o;
    l2_mainloop(smem, A1, A2, B1, B2, blockIdx.x, blockIdx.y, Kd, o);

    const int crow0 = blockIdx.y * 128 + (wid & 1) * 64 + (lane >> 2);
    const int ccol0 = blockIdx.x * 256 + (wid >> 1) * 64 + (lane & 3) * 2;
    #pragma unroll
    for (int tm = 0; tm < 4; tm++)
        #pragma unroll
        for (int n8 = 0; n8 < 8; n8++) {
            const int cc = ccol0 + n8 * 8;
            #pragma unroll
            for (int half = 0; half < 2; half++) {
                const size_t off = (size_t)(crow0 + tm * 16 + half * 8) * N + cc;
                *(float2*)(C + off) = make_float2(alpha * o.acc[tm][n8][half * 2],
                                                  alpha * o.acc[tm][n8][half * 2 + 1]);
            }
        }
}

// Fused k/v: blockIdx.z = 0 -> k (int8 quant out), 1 -> v (fp32 out)
__global__ __launch_bounds__(256, 1)
void hmma2_kv_kernel(const __nv_bfloat16* __restrict__ A1, const __nv_bfloat16* __restrict__ A2,
                     const __nv_bfloat16* Bk1, const __nv_bfloat16* Bk2,
                     const __nv_bfloat16* Bv1, const __nv_bfloat16* Bv2,
                     char* __restrict__ Ka, char* __restrict__ Kb,
                     float* __restrict__ V, int N, int Kd)
{
    extern __shared__ char smem[];
    const int lane = threadIdx.x & 31;
    const int wid  = threadIdx.x >> 5;
    const bool isv = (blockIdx.z != 0);
    L2Out o;
    l2_mainloop(smem, A1, A2, isv ? Bv1 : Bk1, isv ? Bv2 : Bk2,
                blockIdx.x, blockIdx.y, Kd, o);

    const int crow0 = blockIdx.y * 128 + (wid & 1) * 64 + (lane >> 2);
    const int ccol0 = blockIdx.x * 256 + (wid >> 1) * 64 + (lane & 3) * 2;
    #pragma unroll
    for (int tm = 0; tm < 4; tm++)
        #pragma unroll
        for (int n8 = 0; n8 < 8; n8++) {
            const int cc = ccol0 + n8 * 8;
            #pragma unroll
            for (int half = 0; half < 2; half++) {
                const size_t off = (size_t)(crow0 + tm * 16 + half * 8) * N + cc;
                const float v0 = o.acc[tm][n8][half * 2];
                const float v1 = o.acc[tm][n8][half * 2 + 1];
                if (isv) {
                    *(float2*)(V + off) = make_float2(v0, v1);
                } else {
                    char a0, b0, a1, b1;
                    quant2(v0, a0, b0);
                    quant2(v1, a1, b1);
                    *(char2*)(Ka + off) = make_char2(a0, a1);
                    *(char2*)(Kb + off) = make_char2(b0, b1);
                }
            }
        }
}

// ===========================================================================
// L3 HMMA (q): C = (A1+A2+A3)@(B1+B2+B3)^T, 6 products. 256 thr, 8 warps
// 2m x 4n, warp 64x32, BK=32, STG=3. Writes fp32 q + int8 quant pair.
// ===========================================================================
#define L3_STAGE 49152

__global__ __launch_bounds__(256, 1)
void hmma3_kernel(const __nv_bfloat16* __restrict__ A1, const __nv_bfloat16* __restrict__ A2,
                  const __nv_bfloat16* __restrict__ A3,
                  const __nv_bfloat16* __restrict__ B1, const __nv_bfloat16* __restrict__ B2,
                  const __nv_bfloat16* __restrict__ B3,
                  float* __restrict__ C, char* __restrict__ Qa, char* __restrict__ Qb,
                  int N, int Kd)
{
    extern __shared__ char smem[];
    const int tid  = threadIdx.x;
    const int lane = tid & 31;
    const int wid  = tid >> 5;
    const int wm   = wid & 1;
    const int wn   = wid >> 1;
    const int bx = blockIdx.x, by = blockIdx.y;

    const uint32_t sbase = smem_u32(smem);
    const int nstages = Kd >> 5;

    const int lr = tid >> 2, lc = tid & 3;
    const uint32_t so0 = SW((uint32_t)(lr * 64 + lc * 16));
    const uint32_t so1 = SW((uint32_t)((lr + 64) * 64 + lc * 16));
    const size_t ag0 = ((size_t)by * 128 + lr) * Kd + lc * 8;
    const size_t bg0 = ((size_t)bx * 128 + lr) * Kd + lc * 8;
    const size_t rstep = (size_t)64 * Kd;

    const int a_r = lane & 15;
    const int a_h = (lane >> 4) * 16;
    const int b_r = (lane & 7) | ((lane >> 1) & 8);
    const int b_h = ((lane >> 3) & 1) * 16;

    float acc[4][4][4];
    #pragma unroll
    for (int i = 0; i < 4; i++)
        #pragma unroll
        for (int j = 0; j < 4; j++)
            #pragma unroll
            for (int q = 0; q < 4; q++) acc[i][j][q] = 0.0f;

    auto issue = [&](int s) {
        const uint32_t sb = sbase + (uint32_t)((s % STG) * L3_STAGE);
        const size_t kb = (size_t)s * 32;
        cp_async16(sb + so0,         A1 + ag0 + kb);
        cp_async16(sb + so1,         A1 + ag0 + rstep + kb);
        cp_async16(sb + 8192 + so0,  A2 + ag0 + kb);
        cp_async16(sb + 8192 + so1,  A2 + ag0 + rstep + kb);
        cp_async16(sb + 16384 + so0, A3 + ag0 + kb);
        cp_async16(sb + 16384 + so1, A3 + ag0 + rstep + kb);
        cp_async16(sb + 24576 + so0, B1 + bg0 + kb);
        cp_async16(sb + 24576 + so1, B1 + bg0 + rstep + kb);
        cp_async16(sb + 32768 + so0, B2 + bg0 + kb);
        cp_async16(sb + 32768 + so1, B2 + bg0 + rstep + kb);
        cp_async16(sb + 40960 + so0, B3 + bg0 + kb);
        cp_async16(sb + 40960 + so1, B3 + bg0 + rstep + kb);
        cp_commit();
    };

    issue(0);
    if (nstages > 1) issue(1);

    for (int s = 0; s < nstages; s++) {
        if (s + 2 < nstages) issue(s + 2);
        const int after = nstages - 1 - s;
        if (after >= 2)      asm volatile("cp.async.wait_group 2;" ::: "memory");
        else if (after == 1) asm volatile("cp.async.wait_group 1;" ::: "memory");
        else                 asm volatile("cp.async.wait_group 0;" ::: "memory");
        __syncthreads();

        const uint32_t sb = sbase + (uint32_t)((s % STG) * L3_STAGE);
        #pragma unroll
        for (int kk = 0; kk < 2; kk++) {
            uint32_t a1f[4][4], a2f[4][4], a3f[4][4], bf[2][4];
            #pragma unroll
            for (int tm = 0; tm < 4; tm++) {
                const uint32_t off = SW((uint32_t)((wm * 64 + tm * 16 + a_r) * 64 + kk * 32 + a_h));
                ldmx4(a1f[tm], sb + off);
                ldmx4(a2f[tm], sb + 8192 + off);
                ldmx4(a3f[tm], sb + 16384 + off);
            }
            uint32_t boff[2];
            #pragma unroll
            for (int tn = 0; tn < 2; tn++)
                boff[tn] = SW((uint32_t)((wn * 32 + tn * 16 + b_r) * 64 + kk * 32 + b_h));
            #pragma unroll
            for (int tn = 0; tn < 2; tn++) ldmx4(bf[tn], sb + 24576 + boff[tn]);
            #pragma unroll
            for (int tm = 0; tm < 4; tm++)
                #pragma unroll
                for (int n8 = 0; n8 < 4; n8++) {
                    mma16816(acc[tm][n8], a1f[tm], bf[n8 >> 1][(n8 & 1) * 2], bf[n8 >> 1][(n8 & 1) * 2 + 1]);
                    mma16816(acc[tm][n8], a2f[tm], bf[n8 >> 1][(n8 & 1) * 2], bf[n8 >> 1][(n8 & 1) * 2 + 1]);
                    mma16816(acc[tm][n8], a3f[tm], bf[n8 >> 1][(n8 & 1) * 2], bf[n8 >> 1][(n8 & 1) * 2 + 1]);
                }
            #pragma unroll
            for (int tn = 0; tn < 2; tn++) ldmx4(bf[tn], sb + 32768 + boff[tn]);
            #pragma unroll
            for (int tm = 0; tm < 4; tm++)
                #pragma unroll
                for (int n8 = 0; n8 < 4; n8++) {
                    mma16816(acc[tm][n8], a1f[tm], bf[n8 >> 1][(n8 & 1) * 2], bf[n8 >> 1][(n8 & 1) * 2 + 1]);
                    mma16816(acc[tm][n8], a2f[tm], bf[n8 >> 1][(n8 & 1) * 2], bf[n8 >> 1][(n8 & 1) * 2 + 1]);
                }
            #pragma unroll
            for (int tn = 0; tn < 2; tn++) ldmx4(bf[tn], sb + 40960 + boff[tn]);
            #pragma unroll
            for (int tm = 0; tm < 4; tm++)
                #pragma unroll
                for (int n8 = 0; n8 < 4; n8++)
                    mma16816(acc[tm][n8], a1f[tm], bf[n8 >> 1][(n8 & 1) * 2], bf[n8 >> 1][(n8 & 1) * 2 + 1]);
        }
        __syncthreads();
    }

    const int crow0 = by * 128 + wm * 64 + (lane >> 2);
    const int ccol0 = bx * 128 + wn * 32 + (lane & 3) * 2;
    #pragma unroll
    for (int tm = 0; tm < 4; tm++)
        #pragma unroll
        for (int n8 = 0; n8 < 4; n8++) {
            const int cc = ccol0 + n8 * 8;
            #pragma unroll
            for (int half = 0; half < 2; half++) {
                const size_t o = (size_t)(crow0 + tm * 16 + half * 8) * N + cc;
                const float v0 = acc[tm][n8][half * 2];
                const float v1 = acc[tm][n8][half * 2 + 1];
                *(float2*)(C + o) = make_float2(v0, v1);
                char a0, b0, a1, b1;
                quant2(v0, a0, b0);
                quant2(v1, a1, b1);
                *(char2*)(Qa + o) = make_char2(a0, a1);
                *(char2*)(Qb + o) = make_char2(b0, b1);
            }
        }
}

// ===========================================================================
// int8 IMMA S GEMM: S = ((Qa/16+Qb/4064)@(Ka/16+Kb/4064)^T)/32, 4 exact
// int32 products. Block 128x128, 512 thr / 16 warps 4m x 4n, warp 32x32.
// K-step 32 s8 per stage. smem/stage 16KB: qa@0 qb@4K ka@8K kb@12K. STG=4.
// Swizzle: k-half XOR (row>>2)&1 (32B rows, conflict-free ldsm).
// ===========================================================================
#define IS_STG 4
#define IS_STAGE 16384

__global__ __launch_bounds__(512, 1)
void imma_s_kernel(const char* __restrict__ Qa, const char* __restrict__ Qb,
                   const char* __restrict__ Ka, const char* __restrict__ Kb,
                   float* __restrict__ S)
{
    extern __shared__ char smem[];
    const int tid  = threadIdx.x;
    const int lane = tid & 31;
    const int wid  = tid >> 5;
    const int wm   = wid & 3;     // 32-row slot
    const int wn   = wid >> 2;    // 32-col slot
    const int bx = blockIdx.x, by = blockIdx.y;   // bx over NCTX/128, by over BQ/128

    const uint32_t sbase = smem_u32(smem);
    const int nstages = MDIM / 32;   // 32

    // cp.async: tid<256 -> (qa,ka) chunk tid; tid>=256 -> (qb,kb) chunk tid-256
    const int c = tid & 255;
    const int crow = c >> 1, chalf = c & 1;
    const uint32_t so = (uint32_t)(crow * 32 + ((chalf ^ ((crow >> 2) & 1)) << 4));
    const bool hiT = (tid >= 256);
    const char* Aop = hiT ? Qb : Qa;
    const char* Bop = hiT ? Kb : Ka;
    const uint32_t aBase = hiT ? 4096u : 0u;
    const uint32_t bBase = hiT ? 12288u : 8192u;
    const size_t aG = ((size_t)by * 128 + crow) * MDIM + chalf * 16;
    const size_t bG = ((size_t)bx * 128 + crow) * MDIM + chalf * 16;

    // ldsm lane maps (same structure as bf16, 32B rows)
    const int a_r = lane & 15;
    const int a_kh = lane >> 4;                       // 0/1
    const int b_r = (lane & 7) | ((lane >> 1) & 8);
    const int b_kh = (lane >> 3) & 1;

    int aa[2][4][4], ab[2][4][4], bb2[2][4][4];
    #pragma unroll
    for (int i = 0; i < 2; i++)
        #pragma unroll
        for (int j = 0; j < 4; j++)
            #pragma unroll
            for (int q = 0; q < 4; q++) { aa[i][j][q] = 0; ab[i][j][q] = 0; bb2[i][j][q] = 0; }

    auto issue = [&](int s) {
        const uint32_t sb = sbase + (uint32_t)((s % IS_STG) * IS_STAGE);
        const size_t kb = (size_t)s * 32;
        cp_async16(sb + aBase + so, Aop + aG + kb);
        cp_async16(sb + bBase + so, Bop + bG + kb);
        cp_commit();
    };

    issue(0);
    if (nstages > 1) issue(1);
    if (nstages > 2) issue(2);

    for (int s = 0; s < nstages; s++) {
        if (s + 3 < nstages) issue(s + 3);
        const int after = nstages - 1 - s;
        if (after >= 3)      asm volatile("cp.async.wait_group 3;" ::: "memory");
        else if (after == 2) asm volatile("cp.async.wait_group 2;" ::: "memory");
        else if (after == 1) asm volatile("cp.async.wait_group 1;" ::: "memory");
        else                 asm volatile("cp.async.wait_group 0;" ::: "memory");
        __syncthreads();

        const uint32_t sb = sbase + (uint32_t)((s % IS_STG) * IS_STAGE);
        uint32_t fa[2][4], fb[2][4], ga[2][4], gb[2][4];
        #pragma unroll
        for (int tm = 0; tm < 2; tm++) {
            const int row = wm * 32 + tm * 16 + a_r;
            const uint32_t off = (uint32_t)(row * 32 + ((a_kh ^ ((row >> 2) & 1)) << 4));
            ldmx4(fa[tm], sb + off);           // Qa
            ldmx4(fb[tm], sb + 4096 + off);    // Qb
        }
        #pragma unroll
        for (int nh = 0; nh < 2; nh++) {
            const int row = wn * 32 + nh * 16 + b_r;
            const uint32_t off = (uint32_t)(row * 32 + ((b_kh ^ ((row >> 2) & 1)) << 4));
            ldmx4(ga[nh], sb + 8192 + off);    // Ka
            ldmx4(gb[nh], sb + 12288 + off);   // Kb
        }
        #pragma unroll
        for (int tm = 0; tm < 2; tm++)
            #pragma unroll
            for (int g = 0; g < 4; g++) {
                const uint32_t ba0 = ga[g >> 1][(g & 1) * 2], ba1 = ga[g >> 1][(g & 1) * 2 + 1];
                const uint32_t bb0 = gb[g >> 1][(g & 1) * 2], bb1 = gb[g >> 1][(g & 1) * 2 + 1];
                imma16832(aa[tm][g],  fa[tm], ba0, ba1);   // a * a'
                imma16832(ab[tm][g],  fa[tm], bb0, bb1);   // a * b'
                imma16832(ab[tm][g],  fb[tm], ba0, ba1);   // b * a'
                imma16832(bb2[tm][g], fb[tm], bb0, bb1);   // b * b'
            }
        __syncthreads();
    }

    // Combine with scales: q = a/16 + b/4064; S = q.k / 32
    const float W_AA = 1.0f / 8192.0f;
    const float W_AB = 1.0f / (16.0f * QB_SCALE * 32.0f);
    const float W_BB = 1.0f / (QB_SCALE * QB_SCALE * 32.0f);
    const int crow0 = by * 128 + wm * 32 + (lane >> 2);
    const int ccol0 = bx * 128 + wn * 32 + (lane & 3) * 2;
    #pragma unroll
    for (int tm = 0; tm < 2; tm++)
        #pragma unroll
        for (int g = 0; g < 4; g++) {
            const int cc = ccol0 + g * 8;
            #pragma unroll
            for (int half = 0; half < 2; half++) {
                const size_t off = (size_t)(crow0 + tm * 16 + half * 8) * NCTX + cc;
                const int i0 = half * 2;
                const float s0 = (float)aa[tm][g][i0]      * W_AA
                               + (float)ab[tm][g][i0]      * W_AB
                               + (float)bb2[tm][g][i0]     * W_BB;
                const float s1 = (float)aa[tm][g][i0 + 1]  * W_AA
                               + (float)ab[tm][g][i0 + 1]  * W_AB
                               + (float)bb2[tm][g][i0 + 1] * W_BB;
                *(float2*)(S + off) = make_float2(s0, s1);
            }
        }
}

// ===========================================================================
// Vectorized split helpers
// ===========================================================================
__global__ void split_kernel(const float4* __restrict__ x,
                             uint2* __restrict__ hi, uint2* __restrict__ lo, int n4)
{
    const int i = blockIdx.x * blockDim.x + threadIdx.x;
    if (i < n4) {
        const float4 v = x[i];
        const __nv_bfloat16 h0 = __float2bfloat16(v.x), h1 = __float2bfloat16(v.y);
        const __nv_bfloat16 h2 = __float2bfloat16(v.z), h3 = __float2bfloat16(v.w);
        hi[i] = make_uint2(pack_bf2(h0, h1), pack_bf2(h2, h3));
        lo[i] = make_uint2(
            pack_bf2(__float2bfloat16(v.x - __bfloat162float(h0)),
                     __float2bfloat16(v.y - __bfloat162float(h1))),
            pack_bf2(__float2bfloat16(v.z - __bfloat162float(h2)),
                     __float2bfloat16(v.w - __bfloat162float(h3))));
    }
}

__global__ void split3_kernel(const float4* __restrict__ x,
                              uint2* __restrict__ o1, uint2* __restrict__ o2,
                              uint2* __restrict__ o3, int n4)
{
    const int i = blockIdx.x * blockDim.x + threadIdx.x;
    if (i < n4) {
        const float4 v = x[i];
        float f[4] = {v.x, v.y, v.z, v.w};
        __nv_bfloat16 a[4], b[4], c[4];
        #pragma unroll
        for (int j = 0; j < 4; j++) {
            a[j] = __float2bfloat16(f[j]);
            const float r1 = f[j] - __bfloat162float(a[j]);
            b[j] = __float2bfloat16(r1);
            c[j] = __float2bfloat16(r1 - __bfloat162float(b[j]));
        }
        o1[i] = make_uint2(pack_bf2(a[0], a[1]), pack_bf2(a[2], a[3]));
        o2[i] = make_uint2(pack_bf2(b[0], b[1]), pack_bf2(b[2], b[3]));
        o3[i] = make_uint2(pack_bf2(c[0], c[1]), pack_bf2(c[2], c[3]));
    }
}

__global__ void split_transpose_kernel(const float* __restrict__ in,
                                       __nv_bfloat16* __restrict__ hi, __nv_bfloat16* __restrict__ lo,
                                       int rows, int cols)
{
    __shared__ float tile[32][33];
    const int c0 = blockIdx.x * 32, r0 = blockIdx.y * 32;
    const int tx = threadIdx.x, ty = threadIdx.y;
    #pragma unroll
    for (int j = ty; j < 32; j += 8)
        tile[j][tx] = in[(size_t)(r0 + j) * cols + c0 + tx];
    __syncthreads();
    #pragma unroll
    for (int j = ty; j < 32; j += 8) {
        const float v = tile[tx][j];
        const __nv_bfloat16 h = __float2bfloat16(v);
        const size_t o = (size_t)(c0 + j) * rows + r0 + tx;
        hi[o] = h;
        lo[o] = __float2bfloat16(v - __bfloat162float(h));
    }
}

__global__ void split3_transpose_kernel(const float* __restrict__ in,
                                        __nv_bfloat16* __restrict__ h1, __nv_bfloat16* __restrict__ h2,
                                        __nv_bfloat16* __restrict__ h3, int rows, int cols)
{
    __shared__ float tile[32][33];
    const int c0 = blockIdx.x * 32, r0 = blockIdx.y * 32;
    const int tx = threadIdx.x, ty = threadIdx.y;
    #pragma unroll
    for (int j = ty; j < 32; j += 8)
        tile[j][tx] = in[(size_t)(r0 + j) * cols + c0 + tx];
    __syncthreads();
    #pragma unroll
    for (int j = ty; j < 32; j += 8) {
        const float v = tile[tx][j];
        const __nv_bfloat16 a = __float2bfloat16(v);
        const float r1 = v - __bfloat162float(a);
        const __nv_bfloat16 b = __float2bfloat16(r1);
        const size_t o = (size_t)(c0 + j) * rows + r0 + tx;
        h1[o] = a; h2[o] = b;
        h3[o] = __float2bfloat16(r1 - __bfloat162float(b));
    }
}

// ===========================================================================
// Row softmax -> bf16 hi/lo split
// ===========================================================================
__global__ __launch_bounds__(256)
void softmax_split_kernel(const float* __restrict__ S,
                          __nv_bfloat16* __restrict__ P1, __nv_bfloat16* __restrict__ P2)
{
    const int row = blockIdx.x;
    const int t = threadIdx.x;
    const float* Sr = S + (size_t)row * NCTX;
    __shared__ float red[256];

    float vals[NCTX / 256];
    float m = -INFINITY;
    #pragma unroll
    for (int i = 0; i < NCTX / 256; i++) {
        vals[i] = Sr[t + i * 256];
        m = fmaxf(m, vals[i]);
    }
    red[t] = m; __syncthreads();
    #pragma unroll
    for (int s = 128; s > 0; s >>= 1) {
        if (t < s) red[t] = fmaxf(red[t], red[t + s]);
        __syncthreads();
    }
    m = red[0]; __syncthreads();

    float sum = 0.0f;
    #pragma unroll
    for (int i = 0; i < NCTX / 256; i++) {
        vals[i] = __expf(vals[i] - m);
        sum += vals[i];
    }
    red[t] = sum; __syncthreads();
    #pragma unroll
    for (int s = 128; s > 0; s >>= 1) {
        if (t < s) red[t] += red[t + s];
        __syncthreads();
    }
    const float inv = 1.0f / red[0];

    #pragma unroll
    for (int i = 0; i < NCTX / 256; i++) {
        const float p = vals[i] * inv;
        const __nv_bfloat16 h = __float2bfloat16(p);
        const size_t o = (size_t)row * NCTX + t + i * 256;
        P1[o] = h;
        P2[o] = __float2bfloat16(p - __bfloat162float(h));
    }
}

// ===========================================================================
// Fused epilogue
// ===========================================================================
#define EROWS 4
__global__ __launch_bounds__(256)
void epilogue_kernel(const float* __restrict__ O, const float* __restrict__ Q,
                     const float* __restrict__ Whash, const float* __restrict__ bhash,
                     const float* __restrict__ gamma, const float* __restrict__ beta,
                     const float* __restrict__ Wcls, const float* __restrict__ bcls,
                     float* __restrict__ out)
{
    const int b0 = blockIdx.x * EROWS;
    const int t = threadIdx.x;
    __shared__ float att[EROWS][MDIM];
    __shared__ float red[256];
    __shared__ float part[4][EROWS][CDIM];
    __shared__ float code_s[EROWS][CDIM];

    for (int r = 0; r < EROWS; r++) {
        const int b = b0 + r;
        float loc[MDIM / 256];
        float s = 0.0f;
        #pragma unroll
        for (int i = 0; i < MDIM / 256; i++) {
            const int m = t + i * 256;
            loc[i] = __fadd_rn(__fmul_rn(0.1f, O[(size_t)b * MDIM + m]),
                               Q[(size_t)b * MDIM + m]);
            s += loc[i];
        }
        red[t] = s; __syncthreads();
        #pragma unroll
        for (int st = 128; st > 0; st >>= 1) {
            if (t < st) red[t] += red[t + st];
            __syncthreads();
        }
        const float mu = red[0] * (1.0f / MDIM);
        __syncthreads();

        float vs = 0.0f;
        #pragma unroll
        for (int i = 0; i < MDIM / 256; i++) {
            const float d = loc[i] - mu;
            vs += d * d;
        }
        red[t] = vs; __syncthreads();
        #pragma unroll
        for (int st = 128; st > 0; st >>= 1) {
            if (t < st) red[t] += red[t + st];
            __syncthreads();
        }
        const float var = red[0] * (1.0f / MDIM);
        const float rs = 1.0f / sqrtf(var + 1e-6f);
        __syncthreads();

        #pragma unroll
        for (int i = 0; i < MDIM / 256; i++) {
            const int m = t + i * 256;
            att[r][m] = (loc[i] - mu) * rs * gamma[m] + beta[m];
        }
    }
    __syncthreads();

    {
        const int c = t & 63, seg = t >> 6;
        float acc[EROWS] = {0.f, 0.f, 0.f, 0.f};
        const int m0 = seg * (MDIM / 4);
        for (int m = m0; m < m0 + MDIM / 4; m++) {
            const float w = Whash[m * CDIM + c];
            #pragma unroll
            for (int r = 0; r < EROWS; r++) acc[r] += att[r][m] * w;
        }
        #pragma unroll
        for (int r = 0; r < EROWS; r++) part[seg][r][c] = acc[r];
    }
    __syncthreads();

    {
        const int c = t & 63, r = t >> 6;
        const float fh = bhash[c] + part[0][r][c] + part[1][r][c]
                                  + part[2][r][c] + part[3][r][c];
        const float prob = 1.0f / (1.0f + expf(-fh));
        const float hard = (prob > 0.5f) ? 1.0f : 0.0f;
        code_s[r][c] = hard;
        const int b = b0 + r;
        out[(size_t)b * CDIM + c] = hard;
        out[(size_t)BQ * CDIM + (size_t)b * CDIM + c] = prob;
    }
    __syncthreads();

    for (int idx = t; idx < EROWS * KCLS; idx += 256) {
        const int r = idx / KCLS, kk = idx % KCLS;
        float acc = bcls[kk];
        #pragma unroll
        for (int c = 0; c < CDIM; c++)
            acc += code_s[r][c] * Wcls[c * KCLS + kk];
        out[(size_t)BQ * CDIM * 2 + (size_t)(b0 + r) * KCLS + kk] = acc;
    }
}

// ===========================================================================
extern "C" void kernel_launch(void* const* d_in, const int* in_sizes, int n_in,
                              void* d_out, int out_size)
{
    const float* feat   = (const float*)d_in[0];
    const float* emb    = (const float*)d_in[1];
    const float* W_k    = (const float*)d_in[2];
    const float* W_v    = (const float*)d_in[3];
    const float* W_q    = (const float*)d_in[4];
    const float* W_hash = (const float*)d_in[5];
    const float* b_hash = (const float*)d_in[6];
    const float* ln_g   = (const float*)d_in[7];
    const float* ln_b   = (const float*)d_in[8];
    const float* W_cls  = (const float*)d_in[9];
    const float* b_cls  = (const float*)d_in[10];
    float* out = (float*)d_out;

    cudaFuncSetAttribute(hmma2_kernel,    cudaFuncAttributeMaxDynamicSharedMemorySize, STG * L2_STAGE);
    cudaFuncSetAttribute(hmma2_kv_kernel, cudaFuncAttributeMaxDynamicSharedMemorySize, STG * L2_STAGE);
    cudaFuncSetAttribute(hmma3_kernel,    cudaFuncAttributeMaxDynamicSharedMemorySize, STG * L3_STAGE);
    cudaFuncSetAttribute(imma_s_kernel,   cudaFuncAttributeMaxDynamicSharedMemorySize, IS_STG * IS_STAGE);

    __nv_bfloat16 *pe1, *pe2, *pwk1, *pwk2, *pwv1, *pwv2;
    __nv_bfloat16 *pf1, *pf2, *pf3, *pwq1, *pwq2, *pwq3;
    __nv_bfloat16 *pv1, *pv2, *pP1, *pP2;
    char *pqa, *pqb, *pka, *pkb;
    float *pv, *pq, *pS, *pO;
    cudaGetSymbolAddress((void**)&pe1, g_emb1);  cudaGetSymbolAddress((void**)&pe2, g_emb2);
    cudaGetSymbolAddress((void**)&pwk1, g_wk1t); cudaGetSymbolAddress((void**)&pwk2, g_wk2t);
    cudaGetSymbolAddress((void**)&pwv1, g_wv1t); cudaGetSymbolAddress((void**)&pwv2, g_wv2t);
    cudaGetSymbolAddress((void**)&pf1, g_f1);    cudaGetSymbolAddress((void**)&pf2, g_f2);
    cudaGetSymbolAddress((void**)&pf3, g_f3);
    cudaGetSymbolAddress((void**)&pwq1, g_wq1t); cudaGetSymbolAddress((void**)&pwq2, g_wq2t);
    cudaGetSymbolAddress((void**)&pwq3, g_wq3t);
    cudaGetSymbolAddress((void**)&pqa, g_qa);    cudaGetSymbolAddress((void**)&pqb, g_qb);
    cudaGetSymbolAddress((void**)&pka, g_ka);    cudaGetSymbolAddress((void**)&pkb, g_kb);
    cudaGetSymbolAddress((void**)&pv1, g_v1t);   cudaGetSymbolAddress((void**)&pv2, g_v2t);
    cudaGetSymbolAddress((void**)&pP1, g_P1);    cudaGetSymbolAddress((void**)&pP2, g_P2);
    cudaGetSymbolAddress((void**)&pv, g_v);      cudaGetSymbolAddress((void**)&pq, g_q);
    cudaGetSymbolAddress((void**)&pS, g_S);      cudaGetSymbolAddress((void**)&pO, g_O);

    const size_t smem2 = STG * L2_STAGE;
    const size_t smem3 = STG * L3_STAGE;
    const size_t smemS = IS_STG * IS_STAGE;

    // input splits (vectorized)
    split_kernel<<<(NCTX * DDIM / 4) / 256, 256>>>(
        (const float4*)emb, (uint2*)pe1, (uint2*)pe2, NCTX * DDIM / 4);
    split_transpose_kernel<<<dim3(MDIM / 32, DDIM / 32), dim3(32, 8)>>>(W_k, pwk1, pwk2, DDIM, MDIM);
    split_transpose_kernel<<<dim3(MDIM / 32, DDIM / 32), dim3(32, 8)>>>(W_v, pwv1, pwv2, DDIM, MDIM);
    split3_kernel<<<(BQ * DDIM / 4) / 256, 256>>>(
        (const float4*)feat, (uint2*)pf1, (uint2*)pf2, (uint2*)pf3, BQ * DDIM / 4);
    split3_transpose_kernel<<<dim3(MDIM / 32, DDIM / 32), dim3(32, 8)>>>(W_q, pwq1, pwq2, pwq3, DDIM, MDIM);

    // k (int8 quant out) + v (fp32 out) fused into one launch (grid.z)
    hmma2_kv_kernel<<<dim3(MDIM / 256, NCTX / 128, 2), 256, smem2>>>(
        pe1, pe2, pwk1, pwk2, pwv1, pwv2, pka, pkb, pv, MDIM, DDIM);

    // q = feat @ W_q (triple split, 6 products) -> fp32 + int8 quant pair
    hmma3_kernel<<<dim3(MDIM / 128, BQ / 128), 256, smem3>>>(
        pf1, pf2, pf3, pwq1, pwq2, pwq3, pq, pqa, pqb, MDIM, DDIM);

    split_transpose_kernel<<<dim3(MDIM / 32, NCTX / 32), dim3(32, 8)>>>(pv, pv1, pv2, NCTX, MDIM);

    // S = q @ k^T / 32 via int8 IMMA (4 exact int32 products)
    imma_s_kernel<<<dim3(NCTX / 128, BQ / 128), 512, smemS>>>(pqa, pqb, pka, pkb, pS);

    softmax_split_kernel<<<BQ, 256>>>(pS, pP1, pP2);

    // O = P @ v (bf16 x3)
    hmma2_kernel<<<dim3(MDIM / 256, BQ / 128), 256, smem2>>>(
        pP1, pP2, pv1, pv2, pO, MDIM, NCTX, 1.0f);

    epilogue_kernel<<<BQ / EROWS, 256>>>(pO, pq, W_hash, b_hash, ln_g, ln_b, W_cls, b_cls, out);
}

// round 15
// speedup vs baseline: 1.7425x; 1.7425x over previous
#include <cuda_runtime.h>
#include <cuda_bf16.h>
#include <math.h>
#include <stdint.h>

#define BQ   8192
#define NCTX 4096
#define DDIM 2048
#define MDIM 1024
#define CDIM 64
#define KCLS 100

#define SW(off) ((off) ^ (((off) >> 3) & 0x70))

__device__ __forceinline__ uint32_t smem_u32(const void* p) {
    uint32_t a;
    asm("{ .reg .u64 t; cvta.to.shared.u64 t, %1; cvt.u32.u64 %0, t; }" : "=r"(a) : "l"(p));
    return a;
}
__device__ __forceinline__ void cp_async16(uint32_t saddr, const void* gptr) {
    asm volatile("cp.async.cg.shared.global [%0], [%1], 16;" :: "r"(saddr), "l"(gptr) : "memory");
}
__device__ __forceinline__ void cp_commit() {
    asm volatile("cp.async.commit_group;" ::: "memory");
}
__device__ __forceinline__ void ldmx4(uint32_t* r, uint32_t addr) {
    asm volatile("ldmatrix.sync.aligned.m8n8.x4.shared.b16 {%0,%1,%2,%3}, [%4];"
                 : "=r"(r[0]), "=r"(r[1]), "=r"(r[2]), "=r"(r[3]) : "r"(addr));
}
__device__ __forceinline__ void mma16816(float* c, const uint32_t* a, uint32_t b0, uint32_t b1) {
    asm volatile("mma.sync.aligned.m16n8k16.row.col.f32.bf16.bf16.f32 "
                 "{%0,%1,%2,%3}, {%4,%5,%6,%7}, {%8,%9}, {%0,%1,%2,%3};"
                 : "+f"(c[0]), "+f"(c[1]), "+f"(c[2]), "+f"(c[3])
                 : "r"(a[0]), "r"(a[1]), "r"(a[2]), "r"(a[3]), "r"(b0), "r"(b1));
}
__device__ __forceinline__ uint32_t pack_bf2(__nv_bfloat16 a, __nv_bfloat16 b) {
    __nv_bfloat162 t = __halves2bfloat162(a, b);
    return *reinterpret_cast<uint32_t*>(&t);
}

// ===========================================================================
// Device scratch
// ===========================================================================
__device__ __align__(256) __nv_bfloat16 g_emb1[(size_t)NCTX * DDIM];
__device__ __align__(256) __nv_bfloat16 g_emb2[(size_t)NCTX * DDIM];
__device__ __align__(256) __nv_bfloat16 g_wk1t[(size_t)MDIM * DDIM];
__device__ __align__(256) __nv_bfloat16 g_wk2t[(size_t)MDIM * DDIM];
__device__ __align__(256) __nv_bfloat16 g_wv1t[(size_t)MDIM * DDIM];
__device__ __align__(256) __nv_bfloat16 g_wv2t[(size_t)MDIM * DDIM];
__device__ __align__(256) __nv_bfloat16 g_f1[(size_t)BQ * DDIM];
__device__ __align__(256) __nv_bfloat16 g_f2[(size_t)BQ * DDIM];
__device__ __align__(256) __nv_bfloat16 g_f3[(size_t)BQ * DDIM];
__device__ __align__(256) __nv_bfloat16 g_wq1t[(size_t)MDIM * DDIM];
__device__ __align__(256) __nv_bfloat16 g_wq2t[(size_t)MDIM * DDIM];
__device__ __align__(256) __nv_bfloat16 g_wq3t[(size_t)MDIM * DDIM];
__device__ __align__(256) float         g_v [(size_t)NCTX * MDIM];
__device__ __align__(256) float         g_q [(size_t)BQ * MDIM];
__device__ __align__(256) __nv_bfloat16 g_q1[(size_t)BQ * MDIM];
__device__ __align__(256) __nv_bfloat16 g_q2[(size_t)BQ * MDIM];
__device__ __align__(256) __nv_bfloat16 g_k1[(size_t)NCTX * MDIM];
__device__ __align__(256) __nv_bfloat16 g_k2[(size_t)NCTX * MDIM];
__device__ __align__(256) __nv_bfloat16 g_v1t[(size_t)MDIM * NCTX];
__device__ __align__(256) __nv_bfloat16 g_v2t[(size_t)MDIM * NCTX];
__device__ __align__(256) float         g_S [(size_t)BQ * NCTX];
__device__ __align__(256) __nv_bfloat16 g_P1[(size_t)BQ * NCTX];
__device__ __align__(256) __nv_bfloat16 g_P2[(size_t)BQ * NCTX];
__device__ __align__(256) float         g_O [(size_t)BQ * MDIM];

// ===========================================================================
// bf16 HMMA 128x128 mainloop (2-split, 3 products). 256 thr, 8 warps
// (2m x 4n), warp tile 64x32. BK=32, STG=3, stage 32KB:
// A1@0 A2@8K B1@16K B2@24K. 96KB total -> 2 CTAs/SM with <=128 regs.
// ===========================================================================
#define STG 3
#define L2_STAGE 32768

struct L2Out {
    float acc[4][4][4];
};

__device__ __forceinline__ void l2_mainloop(
    char* smem, const __nv_bfloat16* A1, const __nv_bfloat16* A2,
    const __nv_bfloat16* B1, const __nv_bfloat16* B2,
    int bx, int by, int Kd, L2Out& o)
{
    const int tid  = threadIdx.x;
    const int lane = tid & 31;
    const int wid  = tid >> 5;
    const int wm   = wid & 1;
    const int wn   = wid >> 1;

    const uint32_t sbase = smem_u32(smem);
    const int nstages = Kd >> 5;

    const int lr = tid >> 2, lc = tid & 3;
    const uint32_t so0 = SW((uint32_t)(lr * 64 + lc * 16));
    const uint32_t so1 = SW((uint32_t)((lr + 64) * 64 + lc * 16));
    const size_t ag0 = ((size_t)by * 128 + lr) * Kd + lc * 8;
    const size_t bg0 = ((size_t)bx * 128 + lr) * Kd + lc * 8;
    const size_t rstep = (size_t)64 * Kd;

    const int a_r = lane & 15;
    const int a_h = (lane >> 4) * 16;
    const int b_r = (lane & 7) | ((lane >> 1) & 8);
    const int b_h = ((lane >> 3) & 1) * 16;

    #pragma unroll
    for (int i = 0; i < 4; i++)
        #pragma unroll
        for (int j = 0; j < 4; j++)
            #pragma unroll
            for (int q = 0; q < 4; q++) o.acc[i][j][q] = 0.0f;

    auto issue = [&](int s) {
        const uint32_t sb = sbase + (uint32_t)((s % STG) * L2_STAGE);
        const size_t kb = (size_t)s * 32;
        cp_async16(sb + so0,          A1 + ag0 + kb);
        cp_async16(sb + so1,          A1 + ag0 + rstep + kb);
        cp_async16(sb + 8192 + so0,   A2 + ag0 + kb);
        cp_async16(sb + 8192 + so1,   A2 + ag0 + rstep + kb);
        cp_async16(sb + 16384 + so0,  B1 + bg0 + kb);
        cp_async16(sb + 16384 + so1,  B1 + bg0 + rstep + kb);
        cp_async16(sb + 24576 + so0,  B2 + bg0 + kb);
        cp_async16(sb + 24576 + so1,  B2 + bg0 + rstep + kb);
        cp_commit();
    };

    issue(0);
    if (nstages > 1) issue(1);

    for (int s = 0; s < nstages; s++) {
        if (s + 2 < nstages) issue(s + 2);
        const int after = nstages - 1 - s;
        if (after >= 2)      asm volatile("cp.async.wait_group 2;" ::: "memory");
        else if (after == 1) asm volatile("cp.async.wait_group 1;" ::: "memory");
        else                 asm volatile("cp.async.wait_group 0;" ::: "memory");
        __syncthreads();

        const uint32_t sb = sbase + (uint32_t)((s % STG) * L2_STAGE);
        #pragma unroll
        for (int kk = 0; kk < 2; kk++) {
            uint32_t a1f[4][4], a2f[4][4], bf[2][4];
            #pragma unroll
            for (int tm = 0; tm < 4; tm++) {
                const uint32_t off = SW((uint32_t)((wm * 64 + tm * 16 + a_r) * 64 + kk * 32 + a_h));
                ldmx4(a1f[tm], sb + off);
                ldmx4(a2f[tm], sb + 8192 + off);
            }
            uint32_t boff[2];
            #pragma unroll
            for (int tn = 0; tn < 2; tn++)
                boff[tn] = SW((uint32_t)((wn * 32 + tn * 16 + b_r) * 64 + kk * 32 + b_h));
            // B1: a1*b1, a2*b1
            #pragma unroll
            for (int tn = 0; tn < 2; tn++) ldmx4(bf[tn], sb + 16384 + boff[tn]);
            #pragma unroll
            for (int tm = 0; tm < 4; tm++)
                #pragma unroll
                for (int n8 = 0; n8 < 4; n8++) {
                    mma16816(o.acc[tm][n8], a1f[tm], bf[n8 >> 1][(n8 & 1) * 2], bf[n8 >> 1][(n8 & 1) * 2 + 1]);
                    mma16816(o.acc[tm][n8], a2f[tm], bf[n8 >> 1][(n8 & 1) * 2], bf[n8 >> 1][(n8 & 1) * 2 + 1]);
                }
            // B2: a1*b2
            #pragma unroll
            for (int tn = 0; tn < 2; tn++) ldmx4(bf[tn], sb + 24576 + boff[tn]);
            #pragma unroll
            for (int tm = 0; tm < 4; tm++)
                #pragma unroll
                for (int n8 = 0; n8 < 4; n8++)
                    mma16816(o.acc[tm][n8], a1f[tm], bf[n8 >> 1][(n8 & 1) * 2], bf[n8 >> 1][(n8 & 1) * 2 + 1]);
        }
        __syncthreads();
    }
}

// fp32-output variant (S, O GEMMs)
__global__ __launch_bounds__(256, 2)
void hmma2_kernel(const __nv_bfloat16* __restrict__ A1, const __nv_bfloat16* __restrict__ A2,
                  const __nv_bfloat16* __restrict__ B1, const __nv_bfloat16* __restrict__ B2,
                  float* __restrict__ C, int N, int Kd, float alpha)
{
    extern __shared__ char smem[];
    const int lane = threadIdx.x & 31;
    const int wid  = threadIdx.x >> 5;
    L2Out o;
    l2_mainloop(smem, A1, A2, B1, B2, blockIdx.x, blockIdx.y, Kd, o);

    const int crow0 = blockIdx.y * 128 + (wid & 1) * 64 + (lane >> 2);
    const int ccol0 = blockIdx.x * 128 + (wid >> 1) * 32 + (lane & 3) * 2;
    #pragma unroll
    for (int tm = 0; tm < 4; tm++)
        #pragma unroll
        for (int n8 = 0; n8 < 4; n8++) {
            const int cc = ccol0 + n8 * 8;
            #pragma unroll
            for (int half = 0; half < 2; half++) {
                const size_t off = (size_t)(crow0 + tm * 16 + half * 8) * N + cc;
                *(float2*)(C + off) = make_float2(alpha * o.acc[tm][n8][half * 2],
                                                  alpha * o.acc[tm][n8][half * 2 + 1]);
            }
        }
}

// Fused k/v: blockIdx.z = 0 -> k (bf16 split out), 1 -> v (fp32 out)
__global__ __launch_bounds__(256, 2)
void hmma2_kv_kernel(const __nv_bfloat16* __restrict__ A1, const __nv_bfloat16* __restrict__ A2,
                     const __nv_bfloat16* Bk1, const __nv_bfloat16* Bk2,
                     const __nv_bfloat16* Bv1, const __nv_bfloat16* Bv2,
                     __nv_bfloat16* __restrict__ Kh, __nv_bfloat16* __restrict__ Kl,
                     float* __restrict__ V, int N, int Kd)
{
    extern __shared__ char smem[];
    const int lane = threadIdx.x & 31;
    const int wid  = threadIdx.x >> 5;
    const bool isv = (blockIdx.z != 0);
    L2Out o;
    l2_mainloop(smem, A1, A2, isv ? Bv1 : Bk1, isv ? Bv2 : Bk2,
                blockIdx.x, blockIdx.y, Kd, o);

    const int crow0 = blockIdx.y * 128 + (wid & 1) * 64 + (lane >> 2);
    const int ccol0 = blockIdx.x * 128 + (wid >> 1) * 32 + (lane & 3) * 2;
    #pragma unroll
    for (int tm = 0; tm < 4; tm++)
        #pragma unroll
        for (int n8 = 0; n8 < 4; n8++) {
            const int cc = ccol0 + n8 * 8;
            #pragma unroll
            for (int half = 0; half < 2; half++) {
                const size_t off = (size_t)(crow0 + tm * 16 + half * 8) * N + cc;
                const float v0 = o.acc[tm][n8][half * 2];
                const float v1 = o.acc[tm][n8][half * 2 + 1];
                if (isv) {
                    *(float2*)(V + off) = make_float2(v0, v1);
                } else {
                    const __nv_bfloat16 h0 = __float2bfloat16(v0);
                    const __nv_bfloat16 h1 = __float2bfloat16(v1);
                    Kh[off] = h0; Kh[off + 1] = h1;
                    Kl[off]     = __float2bfloat16(v0 - __bfloat162float(h0));
                    Kl[off + 1] = __float2bfloat16(v1 - __bfloat162float(h1));
                }
            }
        }
}

// ===========================================================================
// L3 HMMA (q): C = (A1+A2+A3)@(B1+B2+B3)^T, 6 products. 256 thr, 8 warps
// 2m x 4n, warp 64x32, BK=32, STG=3 (48KB stages, 1 CTA/SM).
// Writes fp32 q + bf16 hi/lo split.
// ===========================================================================
#define L3_STAGE 49152

__global__ __launch_bounds__(256, 1)
void hmma3_kernel(const __nv_bfloat16* __restrict__ A1, const __nv_bfloat16* __restrict__ A2,
                  const __nv_bfloat16* __restrict__ A3,
                  const __nv_bfloat16* __restrict__ B1, const __nv_bfloat16* __restrict__ B2,
                  const __nv_bfloat16* __restrict__ B3,
                  float* __restrict__ C, __nv_bfloat16* __restrict__ Ch, __nv_bfloat16* __restrict__ Cl,
                  int N, int Kd)
{
    extern __shared__ char smem[];
    const int tid  = threadIdx.x;
    const int lane = tid & 31;
    const int wid  = tid >> 5;
    const int wm   = wid & 1;
    const int wn   = wid >> 1;
    const int bx = blockIdx.x, by = blockIdx.y;

    const uint32_t sbase = smem_u32(smem);
    const int nstages = Kd >> 5;

    const int lr = tid >> 2, lc = tid & 3;
    const uint32_t so0 = SW((uint32_t)(lr * 64 + lc * 16));
    const uint32_t so1 = SW((uint32_t)((lr + 64) * 64 + lc * 16));
    const size_t ag0 = ((size_t)by * 128 + lr) * Kd + lc * 8;
    const size_t bg0 = ((size_t)bx * 128 + lr) * Kd + lc * 8;
    const size_t rstep = (size_t)64 * Kd;

    const int a_r = lane & 15;
    const int a_h = (lane >> 4) * 16;
    const int b_r = (lane & 7) | ((lane >> 1) & 8);
    const int b_h = ((lane >> 3) & 1) * 16;

    float acc[4][4][4];
    #pragma unroll
    for (int i = 0; i < 4; i++)
        #pragma unroll
        for (int j = 0; j < 4; j++)
            #pragma unroll
            for (int q = 0; q < 4; q++) acc[i][j][q] = 0.0f;

    auto issue = [&](int s) {
        const uint32_t sb = sbase + (uint32_t)((s % STG) * L3_STAGE);
        const size_t kb = (size_t)s * 32;
        cp_async16(sb + so0,         A1 + ag0 + kb);
        cp_async16(sb + so1,         A1 + ag0 + rstep + kb);
        cp_async16(sb + 8192 + so0,  A2 + ag0 + kb);
        cp_async16(sb + 8192 + so1,  A2 + ag0 + rstep + kb);
        cp_async16(sb + 16384 + so0, A3 + ag0 + kb);
        cp_async16(sb + 16384 + so1, A3 + ag0 + rstep + kb);
        cp_async16(sb + 24576 + so0, B1 + bg0 + kb);
        cp_async16(sb + 24576 + so1, B1 + bg0 + rstep + kb);
        cp_async16(sb + 32768 + so0, B2 + bg0 + kb);
        cp_async16(sb + 32768 + so1, B2 + bg0 + rstep + kb);
        cp_async16(sb + 40960 + so0, B3 + bg0 + kb);
        cp_async16(sb + 40960 + so1, B3 + bg0 + rstep + kb);
        cp_commit();
    };

    issue(0);
    if (nstages > 1) issue(1);

    for (int s = 0; s < nstages; s++) {
        if (s + 2 < nstages) issue(s + 2);
        const int after = nstages - 1 - s;
        if (after >= 2)      asm volatile("cp.async.wait_group 2;" ::: "memory");
        else if (after == 1) asm volatile("cp.async.wait_group 1;" ::: "memory");
        else                 asm volatile("cp.async.wait_group 0;" ::: "memory");
        __syncthreads();

        const uint32_t sb = sbase + (uint32_t)((s % STG) * L3_STAGE);
        #pragma unroll
        for (int kk = 0; kk < 2; kk++) {
            uint32_t a1f[4][4], a2f[4][4], a3f[4][4], bf[2][4];
            #pragma unroll
            for (int tm = 0; tm < 4; tm++) {
                const uint32_t off = SW((uint32_t)((wm * 64 + tm * 16 + a_r) * 64 + kk * 32 + a_h));
                ldmx4(a1f[tm], sb + off);
                ldmx4(a2f[tm], sb + 8192 + off);
                ldmx4(a3f[tm], sb + 16384 + off);
            }
            uint32_t boff[2];
            #pragma unroll
            for (int tn = 0; tn < 2; tn++)
                boff[tn] = SW((uint32_t)((wn * 32 + tn * 16 + b_r) * 64 + kk * 32 + b_h));
            #pragma unroll
            for (int tn = 0; tn < 2; tn++) ldmx4(bf[tn], sb + 24576 + boff[tn]);
            #pragma unroll
            for (int tm = 0; tm < 4; tm++)
                #pragma unroll
                for (int n8 = 0; n8 < 4; n8++) {
                    mma16816(acc[tm][n8], a1f[tm], bf[n8 >> 1][(n8 & 1) * 2], bf[n8 >> 1][(n8 & 1) * 2 + 1]);
                    mma16816(acc[tm][n8], a2f[tm], bf[n8 >> 1][(n8 & 1) * 2], bf[n8 >> 1][(n8 & 1) * 2 + 1]);
                    mma16816(acc[tm][n8], a3f[tm], bf[n8 >> 1][(n8 & 1) * 2], bf[n8 >> 1][(n8 & 1) * 2 + 1]);
                }
            #pragma unroll
            for (int tn = 0; tn < 2; tn++) ldmx4(bf[tn], sb + 32768 + boff[tn]);
            #pragma unroll
            for (int tm = 0; tm < 4; tm++)
                #pragma unroll
                for (int n8 = 0; n8 < 4; n8++) {
                    mma16816(acc[tm][n8], a1f[tm], bf[n8 >> 1][(n8 & 1) * 2], bf[n8 >> 1][(n8 & 1) * 2 + 1]);
                    mma16816(acc[tm][n8], a2f[tm], bf[n8 >> 1][(n8 & 1) * 2], bf[n8 >> 1][(n8 & 1) * 2 + 1]);
                }
            #pragma unroll
            for (int tn = 0; tn < 2; tn++) ldmx4(bf[tn], sb + 40960 + boff[tn]);
            #pragma unroll
            for (int tm = 0; tm < 4; tm++)
                #pragma unroll
                for (int n8 = 0; n8 < 4; n8++)
                    mma16816(acc[tm][n8], a1f[tm], bf[n8 >> 1][(n8 & 1) * 2], bf[n8 >> 1][(n8 & 1) * 2 + 1]);
        }
        __syncthreads();
    }

    const int crow0 = by * 128 + wm * 64 + (lane >> 2);
    const int ccol0 = bx * 128 + wn * 32 + (lane & 3) * 2;
    #pragma unroll
    for (int tm = 0; tm < 4; tm++)
        #pragma unroll
        for (int n8 = 0; n8 < 4; n8++) {
            const int cc = ccol0 + n8 * 8;
            #pragma unroll
            for (int half = 0; half < 2; half++) {
                const size_t o = (size_t)(crow0 + tm * 16 + half * 8) * N + cc;
                const float v0 = acc[tm][n8][half * 2];
                const float v1 = acc[tm][n8][half * 2 + 1];
                *(float2*)(C + o) = make_float2(v0, v1);
                const __nv_bfloat16 h0 = __float2bfloat16(v0);
                const __nv_bfloat16 h1 = __float2bfloat16(v1);
                Ch[o] = h0; Ch[o + 1] = h1;
                Cl[o]     = __float2bfloat16(v0 - __bfloat162float(h0));
                Cl[o + 1] = __float2bfloat16(v1 - __bfloat162float(h1));
            }
        }
}

// ===========================================================================
// Vectorized split helpers
// ===========================================================================
__global__ void split_kernel(const float4* __restrict__ x,
                             uint2* __restrict__ hi, uint2* __restrict__ lo, int n4)
{
    const int i = blockIdx.x * blockDim.x + threadIdx.x;
    if (i < n4) {
        const float4 v = x[i];
        const __nv_bfloat16 h0 = __float2bfloat16(v.x), h1 = __float2bfloat16(v.y);
        const __nv_bfloat16 h2 = __float2bfloat16(v.z), h3 = __float2bfloat16(v.w);
        hi[i] = make_uint2(pack_bf2(h0, h1), pack_bf2(h2, h3));
        lo[i] = make_uint2(
            pack_bf2(__float2bfloat16(v.x - __bfloat162float(h0)),
                     __float2bfloat16(v.y - __bfloat162float(h1))),
            pack_bf2(__float2bfloat16(v.z - __bfloat162float(h2)),
                     __float2bfloat16(v.w - __bfloat162float(h3))));
    }
}

__global__ void split3_kernel(const float4* __restrict__ x,
                              uint2* __restrict__ o1, uint2* __restrict__ o2,
                              uint2* __restrict__ o3, int n4)
{
    const int i = blockIdx.x * blockDim.x + threadIdx.x;
    if (i < n4) {
        const float4 v = x[i];
        float f[4] = {v.x, v.y, v.z, v.w};
        __nv_bfloat16 a[4], b[4], c[4];
        #pragma unroll
        for (int j = 0; j < 4; j++) {
            a[j] = __float2bfloat16(f[j]);
            const float r1 = f[j] - __bfloat162float(a[j]);
            b[j] = __float2bfloat16(r1);
            c[j] = __float2bfloat16(r1 - __bfloat162float(b[j]));
        }
        o1[i] = make_uint2(pack_bf2(a[0], a[1]), pack_bf2(a[2], a[3]));
        o2[i] = make_uint2(pack_bf2(b[0], b[1]), pack_bf2(b[2], b[3]));
        o3[i] = make_uint2(pack_bf2(c[0], c[1]), pack_bf2(c[2], c[3]));
    }
}

__global__ void split_transpose_kernel(const float* __restrict__ in,
                                       __nv_bfloat16* __restrict__ hi, __nv_bfloat16* __restrict__ lo,
                                       int rows, int cols)
{
    __shared__ float tile[32][33];
    const int c0 = blockIdx.x * 32, r0 = blockIdx.y * 32;
    const int tx = threadIdx.x, ty = threadIdx.y;
    #pragma unroll
    for (int j = ty; j < 32; j += 8)
        tile[j][tx] = in[(size_t)(r0 + j) * cols + c0 + tx];
    __syncthreads();
    #pragma unroll
    for (int j = ty; j < 32; j += 8) {
        const float v = tile[tx][j];
        const __nv_bfloat16 h = __float2bfloat16(v);
        const size_t o = (size_t)(c0 + j) * rows + r0 + tx;
        hi[o] = h;
        lo[o] = __float2bfloat16(v - __bfloat162float(h));
    }
}

__global__ void split3_transpose_kernel(const float* __restrict__ in,
                                        __nv_bfloat16* __restrict__ h1, __nv_bfloat16* __restrict__ h2,
                                        __nv_bfloat16* __restrict__ h3, int rows, int cols)
{
    __shared__ float tile[32][33];
    const int c0 = blockIdx.x * 32, r0 = blockIdx.y * 32;
    const int tx = threadIdx.x, ty = threadIdx.y;
    #pragma unroll
    for (int j = ty; j < 32; j += 8)
        tile[j][tx] = in[(size_t)(r0 + j) * cols + c0 + tx];
    __syncthreads();
    #pragma unroll
    for (int j = ty; j < 32; j += 8) {
        const float v = tile[tx][j];
        const __nv_bfloat16 a = __float2bfloat16(v);
        const float r1 = v - __bfloat162float(a);
        const __nv_bfloat16 b = __float2bfloat16(r1);
        const size_t o = (size_t)(c0 + j) * rows + r0 + tx;
        h1[o] = a; h2[o] = b;
        h3[o] = __float2bfloat16(r1 - __bfloat162float(b));
    }
}

// ===========================================================================
// Row softmax -> bf16 hi/lo split
// ===========================================================================
__global__ __launch_bounds__(256)
void softmax_split_kernel(const float* __restrict__ S,
                          __nv_bfloat16* __restrict__ P1, __nv_bfloat16* __restrict__ P2)
{
    const int row = blockIdx.x;
    const int t = threadIdx.x;
    const float* Sr = S + (size_t)row * NCTX;
    __shared__ float red[256];

    float vals[NCTX / 256];
    float m = -INFINITY;
    #pragma unroll
    for (int i = 0; i < NCTX / 256; i++) {
        vals[i] = Sr[t + i * 256];
        m = fmaxf(m, vals[i]);
    }
    red[t] = m; __syncthreads();
    #pragma unroll
    for (int s = 128; s > 0; s >>= 1) {
        if (t < s) red[t] = fmaxf(red[t], red[t + s]);
        __syncthreads();
    }
    m = red[0]; __syncthreads();

    float sum = 0.0f;
    #pragma unroll
    for (int i = 0; i < NCTX / 256; i++) {
        vals[i] = __expf(vals[i] - m);
        sum += vals[i];
    }
    red[t] = sum; __syncthreads();
    #pragma unroll
    for (int s = 128; s > 0; s >>= 1) {
        if (t < s) red[t] += red[t + s];
        __syncthreads();
    }
    const float inv = 1.0f / red[0];

    #pragma unroll
    for (int i = 0; i < NCTX / 256; i++) {
        const float p = vals[i] * inv;
        const __nv_bfloat16 h = __float2bfloat16(p);
        const size_t o = (size_t)row * NCTX + t + i * 256;
        P1[o] = h;
        P2[o] = __float2bfloat16(p - __bfloat162float(h));
    }
}

// ===========================================================================
// Fused epilogue
// ===========================================================================
#define EROWS 4
__global__ __launch_bounds__(256)
void epilogue_kernel(const float* __restrict__ O, const float* __restrict__ Q,
                     const float* __restrict__ Whash, const float* __restrict__ bhash,
                     const float* __restrict__ gamma, const float* __restrict__ beta,
                     const float* __restrict__ Wcls, const float* __restrict__ bcls,
                     float* __restrict__ out)
{
    const int b0 = blockIdx.x * EROWS;
    const int t = threadIdx.x;
    __shared__ float att[EROWS][MDIM];
    __shared__ float red[256];
    __shared__ float part[4][EROWS][CDIM];
    __shared__ float code_s[EROWS][CDIM];

    for (int r = 0; r < EROWS; r++) {
        const int b = b0 + r;
        float loc[MDIM / 256];
        float s = 0.0f;
        #pragma unroll
        for (int i = 0; i < MDIM / 256; i++) {
            const int m = t + i * 256;
            loc[i] = __fadd_rn(__fmul_rn(0.1f, O[(size_t)b * MDIM + m]),
                               Q[(size_t)b * MDIM + m]);
            s += loc[i];
        }
        red[t] = s; __syncthreads();
        #pragma unroll
        for (int st = 128; st > 0; st >>= 1) {
            if (t < st) red[t] += red[t + st];
            __syncthreads();
        }
        const float mu = red[0] * (1.0f / MDIM);
        __syncthreads();

        float vs = 0.0f;
        #pragma unroll
        for (int i = 0; i < MDIM / 256; i++) {
            const float d = loc[i] - mu;
            vs += d * d;
        }
        red[t] = vs; __syncthreads();
        #pragma unroll
        for (int st = 128; st > 0; st >>= 1) {
            if (t < st) red[t] += red[t + st];
            __syncthreads();
        }
        const float var = red[0] * (1.0f / MDIM);
        const float rs = 1.0f / sqrtf(var + 1e-6f);
        __syncthreads();

        #pragma unroll
        for (int i = 0; i < MDIM / 256; i++) {
            const int m = t + i * 256;
            att[r][m] = (loc[i] - mu) * rs * gamma[m] + beta[m];
        }
    }
    __syncthreads();

    {
        const int c = t & 63, seg = t >> 6;
        float acc[EROWS] = {0.f, 0.f, 0.f, 0.f};
        const int m0 = seg * (MDIM / 4);
        for (int m = m0; m < m0 + MDIM / 4; m++) {
            const float w = Whash[m * CDIM + c];
            #pragma unroll
            for (int r = 0; r < EROWS; r++) acc[r] += att[r][m] * w;
        }
        #pragma unroll
        for (int r = 0; r < EROWS; r++) part[seg][r][c] = acc[r];
    }
    __syncthreads();

    {
        const int c = t & 63, r = t >> 6;
        const float fh = bhash[c] + part[0][r][c] + part[1][r][c]
                                  + part[2][r][c] + part[3][r][c];
        const float prob = 1.0f / (1.0f + expf(-fh));
        const float hard = (prob > 0.5f) ? 1.0f : 0.0f;
        code_s[r][c] = hard;
        const int b = b0 + r;
        out[(size_t)b * CDIM + c] = hard;
        out[(size_t)BQ * CDIM + (size_t)b * CDIM + c] = prob;
    }
    __syncthreads();

    for (int idx = t; idx < EROWS * KCLS; idx += 256) {
        const int r = idx / KCLS, kk = idx % KCLS;
        float acc = bcls[kk];
        #pragma unroll
        for (int c = 0; c < CDIM; c++)
            acc += code_s[r][c] * Wcls[c * KCLS + kk];
        out[(size_t)BQ * CDIM * 2 + (size_t)(b0 + r) * KCLS + kk] = acc;
    }
}

// ===========================================================================
extern "C" void kernel_launch(void* const* d_in, const int* in_sizes, int n_in,
                              void* d_out, int out_size)
{
    const float* feat   = (const float*)d_in[0];
    const float* emb    = (const float*)d_in[1];
    const float* W_k    = (const float*)d_in[2];
    const float* W_v    = (const float*)d_in[3];
    const float* W_q    = (const float*)d_in[4];
    const float* W_hash = (const float*)d_in[5];
    const float* b_hash = (const float*)d_in[6];
    const float* ln_g   = (const float*)d_in[7];
    const float* ln_b   = (const float*)d_in[8];
    const float* W_cls  = (const float*)d_in[9];
    const float* b_cls  = (const float*)d_in[10];
    float* out = (float*)d_out;

    cudaFuncSetAttribute(hmma2_kernel,    cudaFuncAttributeMaxDynamicSharedMemorySize, STG * L2_STAGE);
    cudaFuncSetAttribute(hmma2_kv_kernel, cudaFuncAttributeMaxDynamicSharedMemorySize, STG * L2_STAGE);
    cudaFuncSetAttribute(hmma3_kernel,    cudaFuncAttributeMaxDynamicSharedMemorySize, STG * L3_STAGE);

    __nv_bfloat16 *pe1, *pe2, *pwk1, *pwk2, *pwv1, *pwv2;
    __nv_bfloat16 *pf1, *pf2, *pf3, *pwq1, *pwq2, *pwq3;
    __nv_bfloat16 *pq1, *pq2, *pk1, *pk2, *pv1, *pv2, *pP1, *pP2;
    float *pv, *pq, *pS, *pO;
    cudaGetSymbolAddress((void**)&pe1, g_emb1);  cudaGetSymbolAddress((void**)&pe2, g_emb2);
    cudaGetSymbolAddress((void**)&pwk1, g_wk1t); cudaGetSymbolAddress((void**)&pwk2, g_wk2t);
    cudaGetSymbolAddress((void**)&pwv1, g_wv1t); cudaGetSymbolAddress((void**)&pwv2, g_wv2t);
    cudaGetSymbolAddress((void**)&pf1, g_f1);    cudaGetSymbolAddress((void**)&pf2, g_f2);
    cudaGetSymbolAddress((void**)&pf3, g_f3);
    cudaGetSymbolAddress((void**)&pwq1, g_wq1t); cudaGetSymbolAddress((void**)&pwq2, g_wq2t);
    cudaGetSymbolAddress((void**)&pwq3, g_wq3t);
    cudaGetSymbolAddress((void**)&pq1, g_q1);    cudaGetSymbolAddress((void**)&pq2, g_q2);
    cudaGetSymbolAddress((void**)&pk1, g_k1);    cudaGetSymbolAddress((void**)&pk2, g_k2);
    cudaGetSymbolAddress((void**)&pv1, g_v1t);   cudaGetSymbolAddress((void**)&pv2, g_v2t);
    cudaGetSymbolAddress((void**)&pP1, g_P1);    cudaGetSymbolAddress((void**)&pP2, g_P2);
    cudaGetSymbolAddress((void**)&pv, g_v);      cudaGetSymbolAddress((void**)&pq, g_q);
    cudaGetSymbolAddress((void**)&pS, g_S);      cudaGetSymbolAddress((void**)&pO, g_O);

    const size_t smem2 = STG * L2_STAGE;   // 96KB -> 2 CTAs/SM
    const size_t smem3 = STG * L3_STAGE;   // 144KB -> 1 CTA/SM

    // input splits (vectorized)
    split_kernel<<<(NCTX * DDIM / 4) / 256, 256>>>(
        (const float4*)emb, (uint2*)pe1, (uint2*)pe2, NCTX * DDIM / 4);
    split_transpose_kernel<<<dim3(MDIM / 32, DDIM / 32), dim3(32, 8)>>>(W_k, pwk1, pwk2, DDIM, MDIM);
    split_transpose_kernel<<<dim3(MDIM / 32, DDIM / 32), dim3(32, 8)>>>(W_v, pwv1, pwv2, DDIM, MDIM);
    split3_kernel<<<(BQ * DDIM / 4) / 256, 256>>>(
        (const float4*)feat, (uint2*)pf1, (uint2*)pf2, (uint2*)pf3, BQ * DDIM / 4);
    split3_transpose_kernel<<<dim3(MDIM / 32, DDIM / 32), dim3(32, 8)>>>(W_q, pwq1, pwq2, pwq3, DDIM, MDIM);

    // k (bf16 split out) + v (fp32 out) fused (grid.z)
    hmma2_kv_kernel<<<dim3(MDIM / 128, NCTX / 128, 2), 256, smem2>>>(
        pe1, pe2, pwk1, pwk2, pwv1, pwv2, pk1, pk2, pv, MDIM, DDIM);

    // q = feat @ W_q (triple split, 6 products) -> fp32 + hi/lo split
    hmma3_kernel<<<dim3(MDIM / 128, BQ / 128), 256, smem3>>>(
        pf1, pf2, pf3, pwq1, pwq2, pwq3, pq, pq1, pq2, MDIM, DDIM);

    split_transpose_kernel<<<dim3(MDIM / 32, NCTX / 32), dim3(32, 8)>>>(pv, pv1, pv2, NCTX, MDIM);

    // S = q @ k^T / 32
    hmma2_kernel<<<dim3(NCTX / 128, BQ / 128), 256, smem2>>>(
        pq1, pq2, pk1, pk2, pS, NCTX, MDIM, 0.03125f);

    softmax_split_kernel<<<BQ, 256>>>(pS, pP1, pP2);

    // O = P @ v
    hmma2_kernel<<<dim3(MDIM / 128, BQ / 128), 256, smem2>>>(
        pP1, pP2, pv1, pv2, pO, MDIM, NCTX, 1.0f);

    epilogue_kernel<<<BQ / EROWS, 256>>>(pO, pq, W_hash, b_hash, ln_g, ln_b, W_cls, b_cls, out);
}

// round 16
// speedup vs baseline: 2.0213x; 1.1600x over previous
#include <cuda_runtime.h>
#include <cuda_fp16.h>
#include <math.h>
#include <stdint.h>

#define BQ   8192
#define NCTX 4096
#define DDIM 2048
#define MDIM 1024
#define CDIM 64
#define KCLS 100

#define SW(off) ((off) ^ (((off) >> 3) & 0x70))

__device__ __forceinline__ uint32_t smem_u32(const void* p) {
    uint32_t a;
    asm("{ .reg .u64 t; cvta.to.shared.u64 t, %1; cvt.u32.u64 %0, t; }" : "=r"(a) : "l"(p));
    return a;
}
__device__ __forceinline__ void cp_async16(uint32_t saddr, const void* gptr) {
    asm volatile("cp.async.cg.shared.global [%0], [%1], 16;" :: "r"(saddr), "l"(gptr) : "memory");
}
__device__ __forceinline__ void cp_commit() {
    asm volatile("cp.async.commit_group;" ::: "memory");
}
__device__ __forceinline__ void ldmx4(uint32_t* r, uint32_t addr) {
    asm volatile("ldmatrix.sync.aligned.m8n8.x4.shared.b16 {%0,%1,%2,%3}, [%4];"
                 : "=r"(r[0]), "=r"(r[1]), "=r"(r[2]), "=r"(r[3]) : "r"(addr));
}
// fp16 HMMA, fp32 accumulate (full-rate legacy path)
__device__ __forceinline__ void mma16816(float* c, const uint32_t* a, uint32_t b0, uint32_t b1) {
    asm volatile("mma.sync.aligned.m16n8k16.row.col.f32.f16.f16.f32 "
                 "{%0,%1,%2,%3}, {%4,%5,%6,%7}, {%8,%9}, {%0,%1,%2,%3};"
                 : "+f"(c[0]), "+f"(c[1]), "+f"(c[2]), "+f"(c[3])
                 : "r"(a[0]), "r"(a[1]), "r"(a[2]), "r"(a[3]), "r"(b0), "r"(b1));
}
__device__ __forceinline__ uint32_t pack_h2(__half a, __half b) {
    __half2 t = __halves2half2(a, b);
    return *reinterpret_cast<uint32_t*>(&t);
}

// ===========================================================================
// Device scratch (fp16 splits)
// ===========================================================================
__device__ __align__(256) __half g_emb1[(size_t)NCTX * DDIM];
__device__ __align__(256) __half g_emb2[(size_t)NCTX * DDIM];
__device__ __align__(256) __half g_wk1t[(size_t)MDIM * DDIM];
__device__ __align__(256) __half g_wk2t[(size_t)MDIM * DDIM];
__device__ __align__(256) __half g_wv1t[(size_t)MDIM * DDIM];
__device__ __align__(256) __half g_wv2t[(size_t)MDIM * DDIM];
__device__ __align__(256) __half g_f1[(size_t)BQ * DDIM];
__device__ __align__(256) __half g_f2[(size_t)BQ * DDIM];
__device__ __align__(256) __half g_wq1t[(size_t)MDIM * DDIM];
__device__ __align__(256) __half g_wq2t[(size_t)MDIM * DDIM];
__device__ __align__(256) float  g_v [(size_t)NCTX * MDIM];
__device__ __align__(256) float  g_q [(size_t)BQ * MDIM];
__device__ __align__(256) __half g_q1[(size_t)BQ * MDIM];
__device__ __align__(256) __half g_q2[(size_t)BQ * MDIM];
__device__ __align__(256) __half g_k1[(size_t)NCTX * MDIM];
__device__ __align__(256) __half g_k2[(size_t)NCTX * MDIM];
__device__ __align__(256) __half g_v1t[(size_t)MDIM * NCTX];
__device__ __align__(256) __half g_v2t[(size_t)MDIM * NCTX];
__device__ __align__(256) float  g_S [(size_t)BQ * NCTX];
__device__ __align__(256) __half g_P1[(size_t)BQ * NCTX];
__device__ __align__(256) __half g_P2[(size_t)BQ * NCTX];
__device__ __align__(256) float  g_O [(size_t)BQ * MDIM];

// ===========================================================================
// fp16 HMMA 128x128 mainloop (2-split, 3 products). 256 thr, 8 warps
// (2m x 4n), warp tile 64x32. BK=32, STG=3, stage 32KB:
// A1@0 A2@8K B1@16K B2@24K. 96KB total -> 2 CTAs/SM.
// ===========================================================================
#define STG 3
#define L2_STAGE 32768

struct L2Out {
    float acc[4][4][4];
};

__device__ __forceinline__ void l2_mainloop(
    char* smem, const __half* A1, const __half* A2,
    const __half* B1, const __half* B2,
    int bx, int by, int Kd, L2Out& o)
{
    const int tid  = threadIdx.x;
    const int lane = tid & 31;
    const int wid  = tid >> 5;
    const int wm   = wid & 1;
    const int wn   = wid >> 1;

    const uint32_t sbase = smem_u32(smem);
    const int nstages = Kd >> 5;

    const int lr = tid >> 2, lc = tid & 3;
    const uint32_t so0 = SW((uint32_t)(lr * 64 + lc * 16));
    const uint32_t so1 = SW((uint32_t)((lr + 64) * 64 + lc * 16));
    const size_t ag0 = ((size_t)by * 128 + lr) * Kd + lc * 8;
    const size_t bg0 = ((size_t)bx * 128 + lr) * Kd + lc * 8;
    const size_t rstep = (size_t)64 * Kd;

    const int a_r = lane & 15;
    const int a_h = (lane >> 4) * 16;
    const int b_r = (lane & 7) | ((lane >> 1) & 8);
    const int b_h = ((lane >> 3) & 1) * 16;

    #pragma unroll
    for (int i = 0; i < 4; i++)
        #pragma unroll
        for (int j = 0; j < 4; j++)
            #pragma unroll
            for (int q = 0; q < 4; q++) o.acc[i][j][q] = 0.0f;

    auto issue = [&](int s) {
        const uint32_t sb = sbase + (uint32_t)((s % STG) * L2_STAGE);
        const size_t kb = (size_t)s * 32;
        cp_async16(sb + so0,          A1 + ag0 + kb);
        cp_async16(sb + so1,          A1 + ag0 + rstep + kb);
        cp_async16(sb + 8192 + so0,   A2 + ag0 + kb);
        cp_async16(sb + 8192 + so1,   A2 + ag0 + rstep + kb);
        cp_async16(sb + 16384 + so0,  B1 + bg0 + kb);
        cp_async16(sb + 16384 + so1,  B1 + bg0 + rstep + kb);
        cp_async16(sb + 24576 + so0,  B2 + bg0 + kb);
        cp_async16(sb + 24576 + so1,  B2 + bg0 + rstep + kb);
        cp_commit();
    };

    issue(0);
    if (nstages > 1) issue(1);

    for (int s = 0; s < nstages; s++) {
        if (s + 2 < nstages) issue(s + 2);
        const int after = nstages - 1 - s;
        if (after >= 2)      asm volatile("cp.async.wait_group 2;" ::: "memory");
        else if (after == 1) asm volatile("cp.async.wait_group 1;" ::: "memory");
        else                 asm volatile("cp.async.wait_group 0;" ::: "memory");
        __syncthreads();

        const uint32_t sb = sbase + (uint32_t)((s % STG) * L2_STAGE);
        #pragma unroll
        for (int kk = 0; kk < 2; kk++) {
            uint32_t a1f[4][4], a2f[4][4], bf[2][4];
            #pragma unroll
            for (int tm = 0; tm < 4; tm++) {
                const uint32_t off = SW((uint32_t)((wm * 64 + tm * 16 + a_r) * 64 + kk * 32 + a_h));
                ldmx4(a1f[tm], sb + off);
                ldmx4(a2f[tm], sb + 8192 + off);
            }
            uint32_t boff[2];
            #pragma unroll
            for (int tn = 0; tn < 2; tn++)
                boff[tn] = SW((uint32_t)((wn * 32 + tn * 16 + b_r) * 64 + kk * 32 + b_h));
            // B1: a1*b1, a2*b1
            #pragma unroll
            for (int tn = 0; tn < 2; tn++) ldmx4(bf[tn], sb + 16384 + boff[tn]);
            #pragma unroll
            for (int tm = 0; tm < 4; tm++)
                #pragma unroll
                for (int n8 = 0; n8 < 4; n8++) {
                    mma16816(o.acc[tm][n8], a1f[tm], bf[n8 >> 1][(n8 & 1) * 2], bf[n8 >> 1][(n8 & 1) * 2 + 1]);
                    mma16816(o.acc[tm][n8], a2f[tm], bf[n8 >> 1][(n8 & 1) * 2], bf[n8 >> 1][(n8 & 1) * 2 + 1]);
                }
            // B2: a1*b2
            #pragma unroll
            for (int tn = 0; tn < 2; tn++) ldmx4(bf[tn], sb + 24576 + boff[tn]);
            #pragma unroll
            for (int tm = 0; tm < 4; tm++)
                #pragma unroll
                for (int n8 = 0; n8 < 4; n8++)
                    mma16816(o.acc[tm][n8], a1f[tm], bf[n8 >> 1][(n8 & 1) * 2], bf[n8 >> 1][(n8 & 1) * 2 + 1]);
        }
        __syncthreads();
    }
}

// fp32-output variant (S, O GEMMs)
__global__ __launch_bounds__(256, 2)
void hmma2_kernel(const __half* __restrict__ A1, const __half* __restrict__ A2,
                  const __half* __restrict__ B1, const __half* __restrict__ B2,
                  float* __restrict__ C, int N, int Kd, float alpha)
{
    extern __shared__ char smem[];
    const int lane = threadIdx.x & 31;
    const int wid  = threadIdx.x >> 5;
    L2Out o;
    l2_mainloop(smem, A1, A2, B1, B2, blockIdx.x, blockIdx.y, Kd, o);

    const int crow0 = blockIdx.y * 128 + (wid & 1) * 64 + (lane >> 2);
    const int ccol0 = blockIdx.x * 128 + (wid >> 1) * 32 + (lane & 3) * 2;
    #pragma unroll
    for (int tm = 0; tm < 4; tm++)
        #pragma unroll
        for (int n8 = 0; n8 < 4; n8++) {
            const int cc = ccol0 + n8 * 8;
            #pragma unroll
            for (int half = 0; half < 2; half++) {
                const size_t off = (size_t)(crow0 + tm * 16 + half * 8) * N + cc;
                *(float2*)(C + off) = make_float2(alpha * o.acc[tm][n8][half * 2],
                                                  alpha * o.acc[tm][n8][half * 2 + 1]);
            }
        }
}

// Fused k/v: blockIdx.z = 0 -> k (fp16 split out), 1 -> v (fp32 out)
__global__ __launch_bounds__(256, 2)
void hmma2_kv_kernel(const __half* __restrict__ A1, const __half* __restrict__ A2,
                     const __half* Bk1, const __half* Bk2,
                     const __half* Bv1, const __half* Bv2,
                     __half* __restrict__ Kh, __half* __restrict__ Kl,
                     float* __restrict__ V, int N, int Kd)
{
    extern __shared__ char smem[];
    const int lane = threadIdx.x & 31;
    const int wid  = threadIdx.x >> 5;
    const bool isv = (blockIdx.z != 0);
    L2Out o;
    l2_mainloop(smem, A1, A2, isv ? Bv1 : Bk1, isv ? Bv2 : Bk2,
                blockIdx.x, blockIdx.y, Kd, o);

    const int crow0 = blockIdx.y * 128 + (wid & 1) * 64 + (lane >> 2);
    const int ccol0 = blockIdx.x * 128 + (wid >> 1) * 32 + (lane & 3) * 2;
    #pragma unroll
    for (int tm = 0; tm < 4; tm++)
        #pragma unroll
        for (int n8 = 0; n8 < 4; n8++) {
            const int cc = ccol0 + n8 * 8;
            #pragma unroll
            for (int half = 0; half < 2; half++) {
                const size_t off = (size_t)(crow0 + tm * 16 + half * 8) * N + cc;
                const float v0 = o.acc[tm][n8][half * 2];
                const float v1 = o.acc[tm][n8][half * 2 + 1];
                if (isv) {
                    *(float2*)(V + off) = make_float2(v0, v1);
                } else {
                    const __half h0 = __float2half(v0);
                    const __half h1 = __float2half(v1);
                    Kh[off] = h0; Kh[off + 1] = h1;
                    Kl[off]     = __float2half(v0 - __half2float(h0));
                    Kl[off + 1] = __float2half(v1 - __half2float(h1));
                }
            }
        }
}

// q variant: writes fp32 q AND fp16 hi/lo split
__global__ __launch_bounds__(256, 2)
void hmma2_q_kernel(const __half* __restrict__ A1, const __half* __restrict__ A2,
                    const __half* __restrict__ B1, const __half* __restrict__ B2,
                    float* __restrict__ C, __half* __restrict__ Ch, __half* __restrict__ Cl,
                    int N, int Kd)
{
    extern __shared__ char smem[];
    const int lane = threadIdx.x & 31;
    const int wid  = threadIdx.x >> 5;
    L2Out o;
    l2_mainloop(smem, A1, A2, B1, B2, blockIdx.x, blockIdx.y, Kd, o);

    const int crow0 = blockIdx.y * 128 + (wid & 1) * 64 + (lane >> 2);
    const int ccol0 = blockIdx.x * 128 + (wid >> 1) * 32 + (lane & 3) * 2;
    #pragma unroll
    for (int tm = 0; tm < 4; tm++)
        #pragma unroll
        for (int n8 = 0; n8 < 4; n8++) {
            const int cc = ccol0 + n8 * 8;
            #pragma unroll
            for (int half = 0; half < 2; half++) {
                const size_t off = (size_t)(crow0 + tm * 16 + half * 8) * N + cc;
                const float v0 = o.acc[tm][n8][half * 2];
                const float v1 = o.acc[tm][n8][half * 2 + 1];
                *(float2*)(C + off) = make_float2(v0, v1);
                const __half h0 = __float2half(v0);
                const __half h1 = __float2half(v1);
                Ch[off] = h0; Ch[off + 1] = h1;
                Cl[off]     = __float2half(v0 - __half2float(h0));
                Cl[off + 1] = __float2half(v1 - __half2float(h1));
            }
        }
}

// ===========================================================================
// Vectorized split helpers (fp16)
// ===========================================================================
__global__ void split_kernel(const float4* __restrict__ x,
                             uint2* __restrict__ hi, uint2* __restrict__ lo, int n4)
{
    const int i = blockIdx.x * blockDim.x + threadIdx.x;
    if (i < n4) {
        const float4 v = x[i];
        const __half h0 = __float2half(v.x), h1 = __float2half(v.y);
        const __half h2 = __float2half(v.z), h3 = __float2half(v.w);
        hi[i] = make_uint2(pack_h2(h0, h1), pack_h2(h2, h3));
        lo[i] = make_uint2(
            pack_h2(__float2half(v.x - __half2float(h0)),
                    __float2half(v.y - __half2float(h1))),
            pack_h2(__float2half(v.z - __half2float(h2)),
                    __float2half(v.w - __half2float(h3))));
    }
}

__global__ void split_transpose_kernel(const float* __restrict__ in,
                                       __half* __restrict__ hi, __half* __restrict__ lo,
                                       int rows, int cols)
{
    __shared__ float tile[32][33];
    const int c0 = blockIdx.x * 32, r0 = blockIdx.y * 32;
    const int tx = threadIdx.x, ty = threadIdx.y;
    #pragma unroll
    for (int j = ty; j < 32; j += 8)
        tile[j][tx] = in[(size_t)(r0 + j) * cols + c0 + tx];
    __syncthreads();
    #pragma unroll
    for (int j = ty; j < 32; j += 8) {
        const float v = tile[tx][j];
        const __half h = __float2half(v);
        const size_t o = (size_t)(c0 + j) * rows + r0 + tx;
        hi[o] = h;
        lo[o] = __float2half(v - __half2float(h));
    }
}

// ===========================================================================
// Row softmax -> fp16 hi/lo split
// ===========================================================================
__global__ __launch_bounds__(256)
void softmax_split_kernel(const float* __restrict__ S,
                          __half* __restrict__ P1, __half* __restrict__ P2)
{
    const int row = blockIdx.x;
    const int t = threadIdx.x;
    const float* Sr = S + (size_t)row * NCTX;
    __shared__ float red[256];

    float vals[NCTX / 256];
    float m = -INFINITY;
    #pragma unroll
    for (int i = 0; i < NCTX / 256; i++) {
        vals[i] = Sr[t + i * 256];
        m = fmaxf(m, vals[i]);
    }
    red[t] = m; __syncthreads();
    #pragma unroll
    for (int s = 128; s > 0; s >>= 1) {
        if (t < s) red[t] = fmaxf(red[t], red[t + s]);
        __syncthreads();
    }
    m = red[0]; __syncthreads();

    float sum = 0.0f;
    #pragma unroll
    for (int i = 0; i < NCTX / 256; i++) {
        vals[i] = __expf(vals[i] - m);
        sum += vals[i];
    }
    red[t] = sum; __syncthreads();
    #pragma unroll
    for (int s = 128; s > 0; s >>= 1) {
        if (t < s) red[t] += red[t + s];
        __syncthreads();
    }
    const float inv = 1.0f / red[0];

    #pragma unroll
    for (int i = 0; i < NCTX / 256; i++) {
        const float p = vals[i] * inv;
        const __half h = __float2half(p);
        const size_t o = (size_t)row * NCTX + t + i * 256;
        P1[o] = h;
        P2[o] = __float2half(p - __half2float(h));
    }
}

// ===========================================================================
// Fused epilogue
// ===========================================================================
#define EROWS 4
__global__ __launch_bounds__(256)
void epilogue_kernel(const float* __restrict__ O, const float* __restrict__ Q,
                     const float* __restrict__ Whash, const float* __restrict__ bhash,
                     const float* __restrict__ gamma, const float* __restrict__ beta,
                     const float* __restrict__ Wcls, const float* __restrict__ bcls,
                     float* __restrict__ out)
{
    const int b0 = blockIdx.x * EROWS;
    const int t = threadIdx.x;
    __shared__ float att[EROWS][MDIM];
    __shared__ float red[256];
    __shared__ float part[4][EROWS][CDIM];
    __shared__ float code_s[EROWS][CDIM];

    for (int r = 0; r < EROWS; r++) {
        const int b = b0 + r;
        float loc[MDIM / 256];
        float s = 0.0f;
        #pragma unroll
        for (int i = 0; i < MDIM / 256; i++) {
            const int m = t + i * 256;
            loc[i] = __fadd_rn(__fmul_rn(0.1f, O[(size_t)b * MDIM + m]),
                               Q[(size_t)b * MDIM + m]);
            s += loc[i];
        }
        red[t] = s; __syncthreads();
        #pragma unroll
        for (int st = 128; st > 0; st >>= 1) {
            if (t < st) red[t] += red[t + st];
            __syncthreads();
        }
        const float mu = red[0] * (1.0f / MDIM);
        __syncthreads();

        float vs = 0.0f;
        #pragma unroll
        for (int i = 0; i < MDIM / 256; i++) {
            const float d = loc[i] - mu;
            vs += d * d;
        }
        red[t] = vs; __syncthreads();
        #pragma unroll
        for (int st = 128; st > 0; st >>= 1) {
            if (t < st) red[t] += red[t + st];
            __syncthreads();
        }
        const float var = red[0] * (1.0f / MDIM);
        const float rs = 1.0f / sqrtf(var + 1e-6f);
        __syncthreads();

        #pragma unroll
        for (int i = 0; i < MDIM / 256; i++) {
            const int m = t + i * 256;
            att[r][m] = (loc[i] - mu) * rs * gamma[m] + beta[m];
        }
    }
    __syncthreads();

    {
        const int c = t & 63, seg = t >> 6;
        float acc[EROWS] = {0.f, 0.f, 0.f, 0.f};
        const int m0 = seg * (MDIM / 4);
        for (int m = m0; m < m0 + MDIM / 4; m++) {
            const float w = Whash[m * CDIM + c];
            #pragma unroll
            for (int r = 0; r < EROWS; r++) acc[r] += att[r][m] * w;
        }
        #pragma unroll
        for (int r = 0; r < EROWS; r++) part[seg][r][c] = acc[r];
    }
    __syncthreads();

    {
        const int c = t & 63, r = t >> 6;
        const float fh = bhash[c] + part[0][r][c] + part[1][r][c]
                                  + part[2][r][c] + part[3][r][c];
        const float prob = 1.0f / (1.0f + expf(-fh));
        const float hard = (prob > 0.5f) ? 1.0f : 0.0f;
        code_s[r][c] = hard;
        const int b = b0 + r;
        out[(size_t)b * CDIM + c] = hard;
        out[(size_t)BQ * CDIM + (size_t)b * CDIM + c] = prob;
    }
    __syncthreads();

    for (int idx = t; idx < EROWS * KCLS; idx += 256) {
        const int r = idx / KCLS, kk = idx % KCLS;
        float acc = bcls[kk];
        #pragma unroll
        for (int c = 0; c < CDIM; c++)
            acc += code_s[r][c] * Wcls[c * KCLS + kk];
        out[(size_t)BQ * CDIM * 2 + (size_t)(b0 + r) * KCLS + kk] = acc;
    }
}

// ===========================================================================
extern "C" void kernel_launch(void* const* d_in, const int* in_sizes, int n_in,
                              void* d_out, int out_size)
{
    const float* feat   = (const float*)d_in[0];
    const float* emb    = (const float*)d_in[1];
    const float* W_k    = (const float*)d_in[2];
    const float* W_v    = (const float*)d_in[3];
    const float* W_q    = (const float*)d_in[4];
    const float* W_hash = (const float*)d_in[5];
    const float* b_hash = (const float*)d_in[6];
    const float* ln_g   = (const float*)d_in[7];
    const float* ln_b   = (const float*)d_in[8];
    const float* W_cls  = (const float*)d_in[9];
    const float* b_cls  = (const float*)d_in[10];
    float* out = (float*)d_out;

    cudaFuncSetAttribute(hmma2_kernel,    cudaFuncAttributeMaxDynamicSharedMemorySize, STG * L2_STAGE);
    cudaFuncSetAttribute(hmma2_kv_kernel, cudaFuncAttributeMaxDynamicSharedMemorySize, STG * L2_STAGE);
    cudaFuncSetAttribute(hmma2_q_kernel,  cudaFuncAttributeMaxDynamicSharedMemorySize, STG * L2_STAGE);

    __half *pe1, *pe2, *pwk1, *pwk2, *pwv1, *pwv2;
    __half *pf1, *pf2, *pwq1, *pwq2;
    __half *pq1, *pq2, *pk1, *pk2, *pv1, *pv2, *pP1, *pP2;
    float *pv, *pq, *pS, *pO;
    cudaGetSymbolAddress((void**)&pe1, g_emb1);  cudaGetSymbolAddress((void**)&pe2, g_emb2);
    cudaGetSymbolAddress((void**)&pwk1, g_wk1t); cudaGetSymbolAddress((void**)&pwk2, g_wk2t);
    cudaGetSymbolAddress((void**)&pwv1, g_wv1t); cudaGetSymbolAddress((void**)&pwv2, g_wv2t);
    cudaGetSymbolAddress((void**)&pf1, g_f1);    cudaGetSymbolAddress((void**)&pf2, g_f2);
    cudaGetSymbolAddress((void**)&pwq1, g_wq1t); cudaGetSymbolAddress((void**)&pwq2, g_wq2t);
    cudaGetSymbolAddress((void**)&pq1, g_q1);    cudaGetSymbolAddress((void**)&pq2, g_q2);
    cudaGetSymbolAddress((void**)&pk1, g_k1);    cudaGetSymbolAddress((void**)&pk2, g_k2);
    cudaGetSymbolAddress((void**)&pv1, g_v1t);   cudaGetSymbolAddress((void**)&pv2, g_v2t);
    cudaGetSymbolAddress((void**)&pP1, g_P1);    cudaGetSymbolAddress((void**)&pP2, g_P2);
    cudaGetSymbolAddress((void**)&pv, g_v);      cudaGetSymbolAddress((void**)&pq, g_q);
    cudaGetSymbolAddress((void**)&pS, g_S);      cudaGetSymbolAddress((void**)&pO, g_O);

    const size_t smem2 = STG * L2_STAGE;   // 96KB -> 2 CTAs/SM

    // input splits (vectorized, fp16 2-way)
    split_kernel<<<(NCTX * DDIM / 4) / 256, 256>>>(
        (const float4*)emb, (uint2*)pe1, (uint2*)pe2, NCTX * DDIM / 4);
    split_transpose_kernel<<<dim3(MDIM / 32, DDIM / 32), dim3(32, 8)>>>(W_k, pwk1, pwk2, DDIM, MDIM);
    split_transpose_kernel<<<dim3(MDIM / 32, DDIM / 32), dim3(32, 8)>>>(W_v, pwv1, pwv2, DDIM, MDIM);
    split_kernel<<<(BQ * DDIM / 4) / 256, 256>>>(
        (const float4*)feat, (uint2*)pf1, (uint2*)pf2, BQ * DDIM / 4);
    split_transpose_kernel<<<dim3(MDIM / 32, DDIM / 32), dim3(32, 8)>>>(W_q, pwq1, pwq2, DDIM, MDIM);

    // k (fp16 split out) + v (fp32 out) fused (grid.z)
    hmma2_kv_kernel<<<dim3(MDIM / 128, NCTX / 128, 2), 256, smem2>>>(
        pe1, pe2, pwk1, pwk2, pwv1, pwv2, pk1, pk2, pv, MDIM, DDIM);

    // q = feat @ W_q (fp16 2-split, 3 products) -> fp32 + hi/lo split
    hmma2_q_kernel<<<dim3(MDIM / 128, BQ / 128), 256, smem2>>>(
        pf1, pf2, pwq1, pwq2, pq, pq1, pq2, MDIM, DDIM);

    split_transpose_kernel<<<dim3(MDIM / 32, NCTX / 32), dim3(32, 8)>>>(pv, pv1, pv2, NCTX, MDIM);

    // S = q @ k^T / 32
    hmma2_kernel<<<dim3(NCTX / 128, BQ / 128), 256, smem2>>>(
        pq1, pq2, pk1, pk2, pS, NCTX, MDIM, 0.03125f);

    softmax_split_kernel<<<BQ, 256>>>(pS, pP1, pP2);

    // O = P @ v
    hmma2_kernel<<<dim3(MDIM / 128, BQ / 128), 256, smem2>>>(
        pP1, pP2, pv1, pv2, pO, MDIM, NCTX, 1.0f);

    epilogue_kernel<<<BQ / EROWS, 256>>>(pO, pq, W_hash, b_hash, ln_g, ln_b, W_cls, b_cls, out);
}

// round 17
// speedup vs baseline: 2.2236x; 1.1001x over previous
#include <cuda_runtime.h>
#include <cuda_fp16.h>
#include <math.h>
#include <stdint.h>

#define BQ   8192
#define NCTX 4096
#define DDIM 2048
#define MDIM 1024
#define CDIM 64
#define KCLS 100

#define SW(off) ((off) ^ (((off) >> 3) & 0x70))

__device__ __forceinline__ uint32_t smem_u32(const void* p) {
    uint32_t a;
    asm("{ .reg .u64 t; cvta.to.shared.u64 t, %1; cvt.u32.u64 %0, t; }" : "=r"(a) : "l"(p));
    return a;
}
__device__ __forceinline__ void cp_async16(uint32_t saddr, const void* gptr) {
    asm volatile("cp.async.cg.shared.global [%0], [%1], 16;" :: "r"(saddr), "l"(gptr) : "memory");
}
__device__ __forceinline__ void cp_commit() {
    asm volatile("cp.async.commit_group;" ::: "memory");
}
__device__ __forceinline__ void ldmx4(uint32_t* r, uint32_t addr) {
    asm volatile("ldmatrix.sync.aligned.m8n8.x4.shared.b16 {%0,%1,%2,%3}, [%4];"
                 : "=r"(r[0]), "=r"(r[1]), "=r"(r[2]), "=r"(r[3]) : "r"(addr));
}
// fp16 HMMA, fp32 accumulate (full-rate legacy path)
__device__ __forceinline__ void mma16816(float* c, const uint32_t* a, uint32_t b0, uint32_t b1) {
    asm volatile("mma.sync.aligned.m16n8k16.row.col.f32.f16.f16.f32 "
                 "{%0,%1,%2,%3}, {%4,%5,%6,%7}, {%8,%9}, {%0,%1,%2,%3};"
                 : "+f"(c[0]), "+f"(c[1]), "+f"(c[2]), "+f"(c[3])
                 : "r"(a[0]), "r"(a[1]), "r"(a[2]), "r"(a[3]), "r"(b0), "r"(b1));
}
__device__ __forceinline__ uint32_t pack_h2(__half a, __half b) {
    __half2 t = __halves2half2(a, b);
    return *reinterpret_cast<uint32_t*>(&t);
}

// ===========================================================================
// Device scratch (fp16 splits)
// ===========================================================================
__device__ __align__(256) __half g_emb1[(size_t)NCTX * DDIM];
__device__ __align__(256) __half g_emb2[(size_t)NCTX * DDIM];
__device__ __align__(256) __half g_wk1t[(size_t)MDIM * DDIM];
__device__ __align__(256) __half g_wk2t[(size_t)MDIM * DDIM];
__device__ __align__(256) __half g_wv1t[(size_t)MDIM * DDIM];
__device__ __align__(256) __half g_wv2t[(size_t)MDIM * DDIM];
__device__ __align__(256) __half g_f1[(size_t)BQ * DDIM];
__device__ __align__(256) __half g_f2[(size_t)BQ * DDIM];
__device__ __align__(256) __half g_wq1t[(size_t)MDIM * DDIM];
__device__ __align__(256) __half g_wq2t[(size_t)MDIM * DDIM];
__device__ __align__(256) float  g_v [(size_t)NCTX * MDIM];
__device__ __align__(256) float  g_q [(size_t)BQ * MDIM];
__device__ __align__(256) __half g_q1[(size_t)BQ * MDIM];
__device__ __align__(256) __half g_q2[(size_t)BQ * MDIM];
__device__ __align__(256) __half g_k1[(size_t)NCTX * MDIM];
__device__ __align__(256) __half g_k2[(size_t)NCTX * MDIM];
__device__ __align__(256) __half g_v1t[(size_t)MDIM * NCTX];
__device__ __align__(256) __half g_v2t[(size_t)MDIM * NCTX];
__device__ __align__(256) float  g_S [(size_t)BQ * NCTX];
__device__ __align__(256) __half g_P1[(size_t)BQ * NCTX];
__device__ __align__(256) __half g_P2[(size_t)BQ * NCTX];
__device__ __align__(256) float  g_O [(size_t)BQ * MDIM];

// ===========================================================================
// fp16 HMMA 128x128 mainloop (2-split, 3 products). 256 thr, 8 warps
// (2m x 4n), warp tile 64x32. BK=32, STG=3, stage 32KB:
// A1@0 A2@8K B1@16K B2@24K. 96KB total -> 2 CTAs/SM.
// ===========================================================================
#define STG 3
#define L2_STAGE 32768

struct L2Out {
    float acc[4][4][4];
};

__device__ __forceinline__ void l2_mainloop(
    char* smem, const __half* A1, const __half* A2,
    const __half* B1, const __half* B2,
    int bx, int by, int Kd, L2Out& o)
{
    const int tid  = threadIdx.x;
    const int lane = tid & 31;
    const int wid  = tid >> 5;
    const int wm   = wid & 1;
    const int wn   = wid >> 1;

    const uint32_t sbase = smem_u32(smem);
    const int nstages = Kd >> 5;

    const int lr = tid >> 2, lc = tid & 3;
    const uint32_t so0 = SW((uint32_t)(lr * 64 + lc * 16));
    const uint32_t so1 = SW((uint32_t)((lr + 64) * 64 + lc * 16));
    const size_t ag0 = ((size_t)by * 128 + lr) * Kd + lc * 8;
    const size_t bg0 = ((size_t)bx * 128 + lr) * Kd + lc * 8;
    const size_t rstep = (size_t)64 * Kd;

    const int a_r = lane & 15;
    const int a_h = (lane >> 4) * 16;
    const int b_r = (lane & 7) | ((lane >> 1) & 8);
    const int b_h = ((lane >> 3) & 1) * 16;

    #pragma unroll
    for (int i = 0; i < 4; i++)
        #pragma unroll
        for (int j = 0; j < 4; j++)
            #pragma unroll
            for (int q = 0; q < 4; q++) o.acc[i][j][q] = 0.0f;

    auto issue = [&](int s) {
        const uint32_t sb = sbase + (uint32_t)((s % STG) * L2_STAGE);
        const size_t kb = (size_t)s * 32;
        cp_async16(sb + so0,          A1 + ag0 + kb);
        cp_async16(sb + so1,          A1 + ag0 + rstep + kb);
        cp_async16(sb + 8192 + so0,   A2 + ag0 + kb);
        cp_async16(sb + 8192 + so1,   A2 + ag0 + rstep + kb);
        cp_async16(sb + 16384 + so0,  B1 + bg0 + kb);
        cp_async16(sb + 16384 + so1,  B1 + bg0 + rstep + kb);
        cp_async16(sb + 24576 + so0,  B2 + bg0 + kb);
        cp_async16(sb + 24576 + so1,  B2 + bg0 + rstep + kb);
        cp_commit();
    };

    issue(0);
    if (nstages > 1) issue(1);

    for (int s = 0; s < nstages; s++) {
        if (s + 2 < nstages) issue(s + 2);
        const int after = nstages - 1 - s;
        if (after >= 2)      asm volatile("cp.async.wait_group 2;" ::: "memory");
        else if (after == 1) asm volatile("cp.async.wait_group 1;" ::: "memory");
        else                 asm volatile("cp.async.wait_group 0;" ::: "memory");
        __syncthreads();

        const uint32_t sb = sbase + (uint32_t)((s % STG) * L2_STAGE);
        #pragma unroll
        for (int kk = 0; kk < 2; kk++) {
            uint32_t a1f[4][4], a2f[4][4], bf[2][4];
            #pragma unroll
            for (int tm = 0; tm < 4; tm++) {
                const uint32_t off = SW((uint32_t)((wm * 64 + tm * 16 + a_r) * 64 + kk * 32 + a_h));
                ldmx4(a1f[tm], sb + off);
                ldmx4(a2f[tm], sb + 8192 + off);
            }
            uint32_t boff[2];
            #pragma unroll
            for (int tn = 0; tn < 2; tn++)
                boff[tn] = SW((uint32_t)((wn * 32 + tn * 16 + b_r) * 64 + kk * 32 + b_h));
            // B1: a1*b1, a2*b1
            #pragma unroll
            for (int tn = 0; tn < 2; tn++) ldmx4(bf[tn], sb + 16384 + boff[tn]);
            #pragma unroll
            for (int tm = 0; tm < 4; tm++)
                #pragma unroll
                for (int n8 = 0; n8 < 4; n8++) {
                    mma16816(o.acc[tm][n8], a1f[tm], bf[n8 >> 1][(n8 & 1) * 2], bf[n8 >> 1][(n8 & 1) * 2 + 1]);
                    mma16816(o.acc[tm][n8], a2f[tm], bf[n8 >> 1][(n8 & 1) * 2], bf[n8 >> 1][(n8 & 1) * 2 + 1]);
                }
            // B2: a1*b2
            #pragma unroll
            for (int tn = 0; tn < 2; tn++) ldmx4(bf[tn], sb + 24576 + boff[tn]);
            #pragma unroll
            for (int tm = 0; tm < 4; tm++)
                #pragma unroll
                for (int n8 = 0; n8 < 4; n8++)
                    mma16816(o.acc[tm][n8], a1f[tm], bf[n8 >> 1][(n8 & 1) * 2], bf[n8 >> 1][(n8 & 1) * 2 + 1]);
        }
        __syncthreads();
    }
}

// fp32-output variant (S GEMM)
__global__ __launch_bounds__(256, 2)
void hmma2_kernel(const __half* __restrict__ A1, const __half* __restrict__ A2,
                  const __half* __restrict__ B1, const __half* __restrict__ B2,
                  float* __restrict__ C, int N, int Kd, float alpha)
{
    extern __shared__ char smem[];
    const int lane = threadIdx.x & 31;
    const int wid  = threadIdx.x >> 5;
    L2Out o;
    l2_mainloop(smem, A1, A2, B1, B2, blockIdx.x, blockIdx.y, Kd, o);

    const int crow0 = blockIdx.y * 128 + (wid & 1) * 64 + (lane >> 2);
    const int ccol0 = blockIdx.x * 128 + (wid >> 1) * 32 + (lane & 3) * 2;
    #pragma unroll
    for (int tm = 0; tm < 4; tm++)
        #pragma unroll
        for (int n8 = 0; n8 < 4; n8++) {
            const int cc = ccol0 + n8 * 8;
            #pragma unroll
            for (int half = 0; half < 2; half++) {
                const size_t off = (size_t)(crow0 + tm * 16 + half * 8) * N + cc;
                *(float2*)(C + off) = make_float2(alpha * o.acc[tm][n8][half * 2],
                                                  alpha * o.acc[tm][n8][half * 2 + 1]);
            }
        }
}

// Fused k/v: blockIdx.z = 0 -> k (fp16 split out), 1 -> v (fp32 out)
__global__ __launch_bounds__(256, 2)
void hmma2_kv_kernel(const __half* __restrict__ A1, const __half* __restrict__ A2,
                     const __half* Bk1, const __half* Bk2,
                     const __half* Bv1, const __half* Bv2,
                     __half* __restrict__ Kh, __half* __restrict__ Kl,
                     float* __restrict__ V, int N, int Kd)
{
    extern __shared__ char smem[];
    const int lane = threadIdx.x & 31;
    const int wid  = threadIdx.x >> 5;
    const bool isv = (blockIdx.z != 0);
    L2Out o;
    l2_mainloop(smem, A1, A2, isv ? Bv1 : Bk1, isv ? Bv2 : Bk2,
                blockIdx.x, blockIdx.y, Kd, o);

    const int crow0 = blockIdx.y * 128 + (wid & 1) * 64 + (lane >> 2);
    const int ccol0 = blockIdx.x * 128 + (wid >> 1) * 32 + (lane & 3) * 2;
    #pragma unroll
    for (int tm = 0; tm < 4; tm++)
        #pragma unroll
        for (int n8 = 0; n8 < 4; n8++) {
            const int cc = ccol0 + n8 * 8;
            #pragma unroll
            for (int half = 0; half < 2; half++) {
                const size_t off = (size_t)(crow0 + tm * 16 + half * 8) * N + cc;
                const float v0 = o.acc[tm][n8][half * 2];
                const float v1 = o.acc[tm][n8][half * 2 + 1];
                if (isv) {
                    *(float2*)(V + off) = make_float2(v0, v1);
                } else {
                    const __half h0 = __float2half(v0);
                    const __half h1 = __float2half(v1);
                    Kh[off] = h0; Kh[off + 1] = h1;
                    Kl[off]     = __float2half(v0 - __half2float(h0));
                    Kl[off + 1] = __float2half(v1 - __half2float(h1));
                }
            }
        }
}

// q variant: writes fp32 q AND fp16 hi/lo split
__global__ __launch_bounds__(256, 2)
void hmma2_q_kernel(const __half* __restrict__ A1, const __half* __restrict__ A2,
                    const __half* __restrict__ B1, const __half* __restrict__ B2,
                    float* __restrict__ C, __half* __restrict__ Ch, __half* __restrict__ Cl,
                    int N, int Kd)
{
    extern __shared__ char smem[];
    const int lane = threadIdx.x & 31;
    const int wid  = threadIdx.x >> 5;
    L2Out o;
    l2_mainloop(smem, A1, A2, B1, B2, blockIdx.x, blockIdx.y, Kd, o);

    const int crow0 = blockIdx.y * 128 + (wid & 1) * 64 + (lane >> 2);
    const int ccol0 = blockIdx.x * 128 + (wid >> 1) * 32 + (lane & 3) * 2;
    #pragma unroll
    for (int tm = 0; tm < 4; tm++)
        #pragma unroll
        for (int n8 = 0; n8 < 4; n8++) {
            const int cc = ccol0 + n8 * 8;
            #pragma unroll
            for (int half = 0; half < 2; half++) {
                const size_t off = (size_t)(crow0 + tm * 16 + half * 8) * N + cc;
                const float v0 = o.acc[tm][n8][half * 2];
                const float v1 = o.acc[tm][n8][half * 2 + 1];
                *(float2*)(C + off) = make_float2(v0, v1);
                const __half h0 = __float2half(v0);
                const __half h1 = __float2half(v1);
                Ch[off] = h0; Ch[off + 1] = h1;
                Cl[off]     = __float2half(v0 - __half2float(h0));
                Cl[off + 1] = __float2half(v1 - __half2float(h1));
            }
        }
}

// ===========================================================================
// O GEMM: O = (P1+P2) @ v1^T  (2 products, v2 dropped; err ~6e-6 << budget)
// 128x128, 8 warps 2m x 4n, warp 64x32, BK=32, STG=4, stage 24KB:
// A1@0 A2@8K B1@16K. 96KB total -> 2 CTAs/SM.
// ===========================================================================
#define O_STG 4
#define O_STAGE 24576

__global__ __launch_bounds__(256, 2)
void hmma2_o_kernel(const __half* __restrict__ A1, const __half* __restrict__ A2,
                    const __half* __restrict__ B1,
                    float* __restrict__ C, int N, int Kd)
{
    extern __shared__ char smem[];
    const int tid  = threadIdx.x;
    const int lane = tid & 31;
    const int wid  = tid >> 5;
    const int wm   = wid & 1;
    const int wn   = wid >> 1;
    const int bx = blockIdx.x, by = blockIdx.y;

    const uint32_t sbase = smem_u32(smem);
    const int nstages = Kd >> 5;

    const int lr = tid >> 2, lc = tid & 3;
    const uint32_t so0 = SW((uint32_t)(lr * 64 + lc * 16));
    const uint32_t so1 = SW((uint32_t)((lr + 64) * 64 + lc * 16));
    const size_t ag0 = ((size_t)by * 128 + lr) * Kd + lc * 8;
    const size_t bg0 = ((size_t)bx * 128 + lr) * Kd + lc * 8;
    const size_t rstep = (size_t)64 * Kd;

    const int a_r = lane & 15;
    const int a_h = (lane >> 4) * 16;
    const int b_r = (lane & 7) | ((lane >> 1) & 8);
    const int b_h = ((lane >> 3) & 1) * 16;

    float acc[4][4][4];
    #pragma unroll
    for (int i = 0; i < 4; i++)
        #pragma unroll
        for (int j = 0; j < 4; j++)
            #pragma unroll
            for (int q = 0; q < 4; q++) acc[i][j][q] = 0.0f;

    auto issue = [&](int s) {
        const uint32_t sb = sbase + (uint32_t)((s % O_STG) * O_STAGE);
        const size_t kb = (size_t)s * 32;
        cp_async16(sb + so0,          A1 + ag0 + kb);
        cp_async16(sb + so1,          A1 + ag0 + rstep + kb);
        cp_async16(sb + 8192 + so0,   A2 + ag0 + kb);
        cp_async16(sb + 8192 + so1,   A2 + ag0 + rstep + kb);
        cp_async16(sb + 16384 + so0,  B1 + bg0 + kb);
        cp_async16(sb + 16384 + so1,  B1 + bg0 + rstep + kb);
        cp_commit();
    };

    issue(0);
    if (nstages > 1) issue(1);
    if (nstages > 2) issue(2);

    for (int s = 0; s < nstages; s++) {
        if (s + 3 < nstages) issue(s + 3);
        const int after = nstages - 1 - s;
        if (after >= 3)      asm volatile("cp.async.wait_group 3;" ::: "memory");
        else if (after == 2) asm volatile("cp.async.wait_group 2;" ::: "memory");
        else if (after == 1) asm volatile("cp.async.wait_group 1;" ::: "memory");
        else                 asm volatile("cp.async.wait_group 0;" ::: "memory");
        __syncthreads();

        const uint32_t sb = sbase + (uint32_t)((s % O_STG) * O_STAGE);
        #pragma unroll
        for (int kk = 0; kk < 2; kk++) {
            uint32_t a1f[4][4], a2f[4][4], bf[2][4];
            #pragma unroll
            for (int tm = 0; tm < 4; tm++) {
                const uint32_t off = SW((uint32_t)((wm * 64 + tm * 16 + a_r) * 64 + kk * 32 + a_h));
                ldmx4(a1f[tm], sb + off);
                ldmx4(a2f[tm], sb + 8192 + off);
            }
            #pragma unroll
            for (int tn = 0; tn < 2; tn++) {
                const uint32_t off = SW((uint32_t)((wn * 32 + tn * 16 + b_r) * 64 + kk * 32 + b_h));
                ldmx4(bf[tn], sb + 16384 + off);
            }
            #pragma unroll
            for (int tm = 0; tm < 4; tm++)
                #pragma unroll
                for (int n8 = 0; n8 < 4; n8++) {
                    mma16816(acc[tm][n8], a1f[tm], bf[n8 >> 1][(n8 & 1) * 2], bf[n8 >> 1][(n8 & 1) * 2 + 1]);
                    mma16816(acc[tm][n8], a2f[tm], bf[n8 >> 1][(n8 & 1) * 2], bf[n8 >> 1][(n8 & 1) * 2 + 1]);
                }
        }
        __syncthreads();
    }

    const int crow0 = by * 128 + wm * 64 + (lane >> 2);
    const int ccol0 = bx * 128 + wn * 32 + (lane & 3) * 2;
    #pragma unroll
    for (int tm = 0; tm < 4; tm++)
        #pragma unroll
        for (int n8 = 0; n8 < 4; n8++) {
            const int cc = ccol0 + n8 * 8;
            #pragma unroll
            for (int half = 0; half < 2; half++) {
                const size_t off = (size_t)(crow0 + tm * 16 + half * 8) * N + cc;
                *(float2*)(C + off) = make_float2(acc[tm][n8][half * 2],
                                                  acc[tm][n8][half * 2 + 1]);
            }
        }
}

// ===========================================================================
// Vectorized split helpers (fp16)
// ===========================================================================
__global__ void split_kernel(const float4* __restrict__ x,
                             uint2* __restrict__ hi, uint2* __restrict__ lo, int n4)
{
    const int i = blockIdx.x * blockDim.x + threadIdx.x;
    if (i < n4) {
        const float4 v = x[i];
        const __half h0 = __float2half(v.x), h1 = __float2half(v.y);
        const __half h2 = __float2half(v.z), h3 = __float2half(v.w);
        hi[i] = make_uint2(pack_h2(h0, h1), pack_h2(h2, h3));
        lo[i] = make_uint2(
            pack_h2(__float2half(v.x - __half2float(h0)),
                    __float2half(v.y - __half2float(h1))),
            pack_h2(__float2half(v.z - __half2float(h2)),
                    __float2half(v.w - __half2float(h3))));
    }
}

__global__ void split_transpose_kernel(const float* __restrict__ in,
                                       __half* __restrict__ hi, __half* __restrict__ lo,
                                       int rows, int cols)
{
    __shared__ float tile[32][33];
    const int c0 = blockIdx.x * 32, r0 = blockIdx.y * 32;
    const int tx = threadIdx.x, ty = threadIdx.y;
    #pragma unroll
    for (int j = ty; j < 32; j += 8)
        tile[j][tx] = in[(size_t)(r0 + j) * cols + c0 + tx];
    __syncthreads();
    #pragma unroll
    for (int j = ty; j < 32; j += 8) {
        const float v = tile[tx][j];
        const __half h = __float2half(v);
        const size_t o = (size_t)(c0 + j) * rows + r0 + tx;
        hi[o] = h;
        lo[o] = __float2half(v - __half2float(h));
    }
}

// ===========================================================================
// Row softmax -> fp16 hi/lo split
// ===========================================================================
__global__ __launch_bounds__(256)
void softmax_split_kernel(const float* __restrict__ S,
                          __half* __restrict__ P1, __half* __restrict__ P2)
{
    const int row = blockIdx.x;
    const int t = threadIdx.x;
    const float* Sr = S + (size_t)row * NCTX;
    __shared__ float red[256];

    float vals[NCTX / 256];
    float m = -INFINITY;
    #pragma unroll
    for (int i = 0; i < NCTX / 256; i++) {
        vals[i] = Sr[t + i * 256];
        m = fmaxf(m, vals[i]);
    }
    red[t] = m; __syncthreads();
    #pragma unroll
    for (int s = 128; s > 0; s >>= 1) {
        if (t < s) red[t] = fmaxf(red[t], red[t + s]);
        __syncthreads();
    }
    m = red[0]; __syncthreads();

    float sum = 0.0f;
    #pragma unroll
    for (int i = 0; i < NCTX / 256; i++) {
        vals[i] = __expf(vals[i] - m);
        sum += vals[i];
    }
    red[t] = sum; __syncthreads();
    #pragma unroll
    for (int s = 128; s > 0; s >>= 1) {
        if (t < s) red[t] += red[t + s];
        __syncthreads();
    }
    const float inv = 1.0f / red[0];

    #pragma unroll
    for (int i = 0; i < NCTX / 256; i++) {
        const float p = vals[i] * inv;
        const __half h = __float2half(p);
        const size_t o = (size_t)row * NCTX + t + i * 256;
        P1[o] = h;
        P2[o] = __float2half(p - __half2float(h));
    }
}

// ===========================================================================
// Fused epilogue
// ===========================================================================
#define EROWS 4
__global__ __launch_bounds__(256)
void epilogue_kernel(const float* __restrict__ O, const float* __restrict__ Q,
                     const float* __restrict__ Whash, const float* __restrict__ bhash,
                     const float* __restrict__ gamma, const float* __restrict__ beta,
                     const float* __restrict__ Wcls, const float* __restrict__ bcls,
                     float* __restrict__ out)
{
    const int b0 = blockIdx.x * EROWS;
    const int t = threadIdx.x;
    __shared__ float att[EROWS][MDIM];
    __shared__ float red[256];
    __shared__ float part[4][EROWS][CDIM];
    __shared__ float code_s[EROWS][CDIM];

    for (int r = 0; r < EROWS; r++) {
        const int b = b0 + r;
        float loc[MDIM / 256];
        float s = 0.0f;
        #pragma unroll
        for (int i = 0; i < MDIM / 256; i++) {
            const int m = t + i * 256;
            loc[i] = __fadd_rn(__fmul_rn(0.1f, O[(size_t)b * MDIM + m]),
                               Q[(size_t)b * MDIM + m]);
            s += loc[i];
        }
        red[t] = s; __syncthreads();
        #pragma unroll
        for (int st = 128; st > 0; st >>= 1) {
            if (t < st) red[t] += red[t + st];
            __syncthreads();
        }
        const float mu = red[0] * (1.0f / MDIM);
        __syncthreads();

        float vs = 0.0f;
        #pragma unroll
        for (int i = 0; i < MDIM / 256; i++) {
            const float d = loc[i] - mu;
            vs += d * d;
        }
        red[t] = vs; __syncthreads();
        #pragma unroll
        for (int st = 128; st > 0; st >>= 1) {
            if (t < st) red[t] += red[t + st];
            __syncthreads();
        }
        const float var = red[0] * (1.0f / MDIM);
        const float rs = 1.0f / sqrtf(var + 1e-6f);
        __syncthreads();

        #pragma unroll
        for (int i = 0; i < MDIM / 256; i++) {
            const int m = t + i * 256;
            att[r][m] = (loc[i] - mu) * rs * gamma[m] + beta[m];
        }
    }
    __syncthreads();

    {
        const int c = t & 63, seg = t >> 6;
        float acc[EROWS] = {0.f, 0.f, 0.f, 0.f};
        const int m0 = seg * (MDIM / 4);
        for (int m = m0; m < m0 + MDIM / 4; m++) {
            const float w = Whash[m * CDIM + c];
            #pragma unroll
            for (int r = 0; r < EROWS; r++) acc[r] += att[r][m] * w;
        }
        #pragma unroll
        for (int r = 0; r < EROWS; r++) part[seg][r][c] = acc[r];
    }
    __syncthreads();

    {
        const int c = t & 63, r = t >> 6;
        const float fh = bhash[c] + part[0][r][c] + part[1][r][c]
                                  + part[2][r][c] + part[3][r][c];
        const float prob = 1.0f / (1.0f + expf(-fh));
        const float hard = (prob > 0.5f) ? 1.0f : 0.0f;
        code_s[r][c] = hard;
        const int b = b0 + r;
        out[(size_t)b * CDIM + c] = hard;
        out[(size_t)BQ * CDIM + (size_t)b * CDIM + c] = prob;
    }
    __syncthreads();

    for (int idx = t; idx < EROWS * KCLS; idx += 256) {
        const int r = idx / KCLS, kk = idx % KCLS;
        float acc = bcls[kk];
        #pragma unroll
        for (int c = 0; c < CDIM; c++)
            acc += code_s[r][c] * Wcls[c * KCLS + kk];
        out[(size_t)BQ * CDIM * 2 + (size_t)(b0 + r) * KCLS + kk] = acc;
    }
}

// ===========================================================================
extern "C" void kernel_launch(void* const* d_in, const int* in_sizes, int n_in,
                              void* d_out, int out_size)
{
    const float* feat   = (const float*)d_in[0];
    const float* emb    = (const float*)d_in[1];
    const float* W_k    = (const float*)d_in[2];
    const float* W_v    = (const float*)d_in[3];
    const float* W_q    = (const float*)d_in[4];
    const float* W_hash = (const float*)d_in[5];
    const float* b_hash = (const float*)d_in[6];
    const float* ln_g   = (const float*)d_in[7];
    const float* ln_b   = (const float*)d_in[8];
    const float* W_cls  = (const float*)d_in[9];
    const float* b_cls  = (const float*)d_in[10];
    float* out = (float*)d_out;

    cudaFuncSetAttribute(hmma2_kernel,    cudaFuncAttributeMaxDynamicSharedMemorySize, STG * L2_STAGE);
    cudaFuncSetAttribute(hmma2_kv_kernel, cudaFuncAttributeMaxDynamicSharedMemorySize, STG * L2_STAGE);
    cudaFuncSetAttribute(hmma2_q_kernel,  cudaFuncAttributeMaxDynamicSharedMemorySize, STG * L2_STAGE);
    cudaFuncSetAttribute(hmma2_o_kernel,  cudaFuncAttributeMaxDynamicSharedMemorySize, O_STG * O_STAGE);

    __half *pe1, *pe2, *pwk1, *pwk2, *pwv1, *pwv2;
    __half *pf1, *pf2, *pwq1, *pwq2;
    __half *pq1, *pq2, *pk1, *pk2, *pv1, *pv2, *pP1, *pP2;
    float *pv, *pq, *pS, *pO;
    cudaGetSymbolAddress((void**)&pe1, g_emb1);  cudaGetSymbolAddress((void**)&pe2, g_emb2);
    cudaGetSymbolAddress((void**)&pwk1, g_wk1t); cudaGetSymbolAddress((void**)&pwk2, g_wk2t);
    cudaGetSymbolAddress((void**)&pwv1, g_wv1t); cudaGetSymbolAddress((void**)&pwv2, g_wv2t);
    cudaGetSymbolAddress((void**)&pf1, g_f1);    cudaGetSymbolAddress((void**)&pf2, g_f2);
    cudaGetSymbolAddress((void**)&pwq1, g_wq1t); cudaGetSymbolAddress((void**)&pwq2, g_wq2t);
    cudaGetSymbolAddress((void**)&pq1, g_q1);    cudaGetSymbolAddress((void**)&pq2, g_q2);
    cudaGetSymbolAddress((void**)&pk1, g_k1);    cudaGetSymbolAddress((void**)&pk2, g_k2);
    cudaGetSymbolAddress((void**)&pv1, g_v1t);   cudaGetSymbolAddress((void**)&pv2, g_v2t);
    cudaGetSymbolAddress((void**)&pP1, g_P1);    cudaGetSymbolAddress((void**)&pP2, g_P2);
    cudaGetSymbolAddress((void**)&pv, g_v);      cudaGetSymbolAddress((void**)&pq, g_q);
    cudaGetSymbolAddress((void**)&pS, g_S);      cudaGetSymbolAddress((void**)&pO, g_O);

    const size_t smem2 = STG * L2_STAGE;     // 96KB -> 2 CTAs/SM
    const size_t smemO = O_STG * O_STAGE;    // 96KB -> 2 CTAs/SM

    // input splits (vectorized, fp16 2-way)
    split_kernel<<<(NCTX * DDIM / 4) / 256, 256>>>(
        (const float4*)emb, (uint2*)pe1, (uint2*)pe2, NCTX * DDIM / 4);
    split_transpose_kernel<<<dim3(MDIM / 32, DDIM / 32), dim3(32, 8)>>>(W_k, pwk1, pwk2, DDIM, MDIM);
    split_transpose_kernel<<<dim3(MDIM / 32, DDIM / 32), dim3(32, 8)>>>(W_v, pwv1, pwv2, DDIM, MDIM);
    split_kernel<<<(BQ * DDIM / 4) / 256, 256>>>(
        (const float4*)feat, (uint2*)pf1, (uint2*)pf2, BQ * DDIM / 4);
    split_transpose_kernel<<<dim3(MDIM / 32, DDIM / 32), dim3(32, 8)>>>(W_q, pwq1, pwq2, DDIM, MDIM);

    // k (fp16 split out) + v (fp32 out) fused (grid.z)
    hmma2_kv_kernel<<<dim3(MDIM / 128, NCTX / 128, 2), 256, smem2>>>(
        pe1, pe2, pwk1, pwk2, pwv1, pwv2, pk1, pk2, pv, MDIM, DDIM);

    // q = feat @ W_q (fp16 2-split, 3 products) -> fp32 + hi/lo split
    hmma2_q_kernel<<<dim3(MDIM / 128, BQ / 128), 256, smem2>>>(
        pf1, pf2, pwq1, pwq2, pq, pq1, pq2, MDIM, DDIM);

    split_transpose_kernel<<<dim3(MDIM / 32, NCTX / 32), dim3(32, 8)>>>(pv, pv1, pv2, NCTX, MDIM);

    // S = q @ k^T / 32 (3 products)
    hmma2_kernel<<<dim3(NCTX / 128, BQ / 128), 256, smem2>>>(
        pq1, pq2, pk1, pk2, pS, NCTX, MDIM, 0.03125f);

    softmax_split_kernel<<<BQ, 256>>>(pS, pP1, pP2);

    // O = (P1+P2) @ v1 (2 products)
    hmma2_o_kernel<<<dim3(MDIM / 128, BQ / 128), 256, smemO>>>(
        pP1, pP2, pv1, pO, MDIM, NCTX);

    epilogue_kernel<<<BQ / EROWS, 256>>>(pO, pq, W_hash, b_hash, ln_g, ln_b, W_cls, b_cls, out);
}